// round 8
// baseline (speedup 1.0000x reference)
#include <cuda_runtime.h>
#include <cuda_bf16.h>
#include <math.h>
#include <stdint.h>

#define Nn    20000
#define Ee    120000
#define INF_  3000
#define HIDF  512
#define OUTF  30
#define NH    3
#define NDOMc 4
#define MHc   64
#define NLABc 20
#define EPSBN 1e-5f
#define KPAD  3008                 // 3000 padded to multiple of 32

// ---------------- scratch (static device memory; no allocations) ----------------
__device__ float    g_x[(size_t)Nn * INF_];
__device__ float    g_H[(size_t)Nn * NH * HIDF];
__device__ float    g_acc1[(size_t)Nn * NH * HIDF];
__device__ float    g_h1[(size_t)Nn * HIDF];
__device__ float    g_H2[(size_t)Nn * NH * OUTF];
__device__ float    g_acc2[(size_t)Nn * NH * OUTF];
__device__ float    g_als1[Nn * NH], g_ald1[Nn * NH];
__device__ float    g_als2[Nn * NH], g_ald2[Nn * NH];
__device__ float    g_e1[(size_t)Ee * NH];
__device__ float    g_e2[(size_t)Ee * NH];
__device__ unsigned g_mkey1[Nn * NH], g_mkey2[Nn * NH];
__device__ float    g_den1[Nn * NH], g_den2[Nn * NH];
__device__ float    g_bnsum[INF_], g_bnsum2[INF_];
__device__ float    g_dsum[NDOMc * INF_], g_dsum2[NDOMc * INF_];
__device__ float    g_cnt[NDOMc];
__device__ __align__(256) __nv_bfloat16 g_Ahi[(size_t)Nn * KPAD];
__device__ __align__(256) __nv_bfloat16 g_Alo[(size_t)Nn * KPAD];
__device__ __align__(256) __nv_bfloat16 g_Whi[(size_t)INF_ * KPAD];
__device__ __align__(256) __nv_bfloat16 g_Wlo[(size_t)INF_ * KPAD];

// ---------------- helpers ----------------
__device__ __forceinline__ unsigned f2o(float f) {
    unsigned u = __float_as_uint(f);
    return (u & 0x80000000u) ? ~u : (u | 0x80000000u);
}
__device__ __forceinline__ float o2f(unsigned k) {
    return (k & 0x80000000u) ? __uint_as_float(k ^ 0x80000000u) : __uint_as_float(~k);
}
__device__ __forceinline__ float eluf(float v) { return v > 0.f ? v : (expf(v) - 1.f); }

__device__ __forceinline__ uint32_t smem_u32(const void* p) {
    uint32_t a;
    asm("{ .reg .u64 t; cvta.to.shared.u64 t, %1; cvt.u32.u64 %0, t; }" : "=r"(a) : "l"(p));
    return a;
}

__device__ __forceinline__ void cp16(uint32_t dst, const void* src, int ok) {
    asm volatile("cp.async.cg.shared.global [%0], [%1], 16, %2;"
                 :: "r"(dst), "l"(src), "r"(ok ? 16 : 0) : "memory");
}
#define CP_COMMIT() asm volatile("cp.async.commit_group;" ::: "memory")
#define CP_WAIT1()  asm volatile("cp.async.wait_group 1;" ::: "memory")

// non-volatile: pure register op, ptxas may schedule freely
__device__ __forceinline__ void mma16816(float* c, const uint32_t* a, const uint32_t* b) {
    asm("mma.sync.aligned.m16n8k16.row.col.f32.bf16.bf16.f32 "
        "{%0,%1,%2,%3},{%4,%5,%6,%7},{%8,%9},{%0,%1,%2,%3};"
        : "+f"(c[0]), "+f"(c[1]), "+f"(c[2]), "+f"(c[3])
        : "r"(a[0]), "r"(a[1]), "r"(a[2]), "r"(a[3]), "r"(b[0]), "r"(b[1]));
}
__device__ __forceinline__ void ldsm_x4(uint32_t* r, uint32_t addr) {
    asm volatile("ldmatrix.sync.aligned.m8n8.x4.shared.b16 {%0,%1,%2,%3}, [%4];"
                 : "=r"(r[0]), "=r"(r[1]), "=r"(r[2]), "=r"(r[3]) : "r"(addr));
}

// ---------------- split kernels ----------------
__global__ void k_splitA4(const float* __restrict__ X, __nv_bfloat16* __restrict__ hi,
                          __nv_bfloat16* __restrict__ lo, int M, int K) {
    size_t i4 = (size_t)blockIdx.x * blockDim.x + threadIdx.x;
    const int kq = KPAD / 4;
    if (i4 >= (size_t)M * kq) return;
    int m = (int)(i4 / kq), k4 = (int)(i4 % kq) * 4;
    const float* row = X + (size_t)m * K;
    float v0, v1, v2, v3;
    if (k4 + 3 < K) {
        float4 f = *reinterpret_cast<const float4*>(row + k4);
        v0 = f.x; v1 = f.y; v2 = f.z; v3 = f.w;
    } else {
        v0 = (k4 + 0 < K) ? row[k4 + 0] : 0.f;
        v1 = (k4 + 1 < K) ? row[k4 + 1] : 0.f;
        v2 = (k4 + 2 < K) ? row[k4 + 2] : 0.f;
        v3 = (k4 + 3 < K) ? row[k4 + 3] : 0.f;
    }
    __nv_bfloat16 h0 = __float2bfloat16(v0), h1 = __float2bfloat16(v1);
    __nv_bfloat16 h2 = __float2bfloat16(v2), h3 = __float2bfloat16(v3);
    __nv_bfloat162 hp0 = __nv_bfloat162(h0, h1), hp1 = __nv_bfloat162(h2, h3);
    __nv_bfloat162 lp0 = __nv_bfloat162(__float2bfloat16(v0 - __bfloat162float(h0)),
                                        __float2bfloat16(v1 - __bfloat162float(h1)));
    __nv_bfloat162 lp1 = __nv_bfloat162(__float2bfloat16(v2 - __bfloat162float(h2)),
                                        __float2bfloat16(v3 - __bfloat162float(h3)));
    size_t o = (size_t)m * KPAD + k4;
    uint2 hv, lv;
    hv.x = *(uint32_t*)&hp0; hv.y = *(uint32_t*)&hp1;
    lv.x = *(uint32_t*)&lp0; lv.y = *(uint32_t*)&lp1;
    *reinterpret_cast<uint2*>(hi + o) = hv;
    *reinterpret_cast<uint2*>(lo + o) = lv;
}

// W[K, N] f32 -> WT hi/lo [N, KPAD] bf16 (zero pad beyond K)
__global__ void k_splitWT(const float* __restrict__ W, __nv_bfloat16* __restrict__ hi,
                          __nv_bfloat16* __restrict__ lo, int K, int Nmat) {
    __shared__ float t[32][33];
    int kb = blockIdx.x * 32, nb = blockIdx.y * 32;
    int rk = kb + threadIdx.y, rn = nb + threadIdx.x;
    t[threadIdx.y][threadIdx.x] = (rk < K && rn < Nmat) ? W[(size_t)rk * Nmat + rn] : 0.f;
    __syncthreads();
    int wn = nb + threadIdx.y, wk = kb + threadIdx.x;
    if (wn < Nmat && wk < KPAD) {
        float x = t[threadIdx.x][threadIdx.y];
        __nv_bfloat16 h = __float2bfloat16(x);
        size_t o = (size_t)wn * KPAD + wk;
        hi[o] = h;
        lo[o] = __float2bfloat16(x - __bfloat162float(h));
    }
}

// ------- mma.sync bf16x3 GEMM: 128 thr, warp tile 64x64, 2 CTAs/SM -------
#define ROWB      80                     // 64B data + 16B pad
#define TILE_PAD  (128 * ROWB)           // 10240 B
#define STAGE_B   (4 * TILE_PAD)         // 40960 B
#define GSMEM     (2 * STAGE_B)          // 81920 B

__device__ __forceinline__ void ld_stage(
    uint32_t sb,
    const __nv_bfloat16* __restrict__ Ahi, const __nv_bfloat16* __restrict__ Alo,
    const __nv_bfloat16* __restrict__ Bhi, const __nv_bfloat16* __restrict__ Blo,
    int m0, int n0, int M, int Nmat, int kb, int tid)
{
    int tile = tid >> 5;          // 0=Ahi 1=Alo 2=Bhi 3=Blo
    int r0 = (tid & 31) * 4;      // four rows per thread
    const __nv_bfloat16* base;
    int lim, off;
    if (tile < 2) { base = (tile == 0) ? Ahi : Alo; lim = M;    off = m0; }
    else          { base = (tile == 2) ? Bhi : Blo; lim = Nmat; off = n0; }
#pragma unroll
    for (int rr = 0; rr < 4; rr++) {
        int row = r0 + rr;
        int grow = off + row;
        int ok = grow < lim;
        const __nv_bfloat16* g = base + (size_t)(ok ? grow : 0) * KPAD + kb;
        uint32_t so = sb + (uint32_t)tile * TILE_PAD + (uint32_t)row * ROWB;
        cp16(so,      g,      ok);
        cp16(so + 16, g + 8,  ok);
        cp16(so + 32, g + 16, ok);
        cp16(so + 48, g + 24, ok);
    }
}

__global__ void __launch_bounds__(128, 2) gemm_mma3(
    const __nv_bfloat16* __restrict__ Ahi, const __nv_bfloat16* __restrict__ Alo,
    const __nv_bfloat16* __restrict__ Bhi, const __nv_bfloat16* __restrict__ Blo,
    const float* __restrict__ bias, float* __restrict__ C,
    int M, int Nmat, int nNt)
{
    extern __shared__ char smem[];
    uint32_t sbase = smem_u32(smem);
    int tid = threadIdx.x, lane = tid & 31, wid = tid >> 5;
    int wm = wid >> 1, wn = wid & 1;          // warp grid 2x2; warp tile 64x64
    int gID = lane >> 2, tg = lane & 3;
    int bid = blockIdx.x;
    int nt = bid % nNt, mt = bid / nNt;
    int m0 = mt * 128, n0 = nt * 128;
    const int nK = KPAD / 32;                 // 94

    float acc[4][8][4];
#pragma unroll
    for (int i = 0; i < 4; i++)
#pragma unroll
        for (int j = 0; j < 8; j++)
#pragma unroll
            for (int q = 0; q < 4; q++) acc[i][j][q] = 0.f;

    // prologue: stage 0 in flight
    ld_stage(sbase, Ahi, Alo, Bhi, Blo, m0, n0, M, Nmat, 0, tid);
    CP_COMMIT();

    // ldmatrix base offsets (within a stage)
    uint32_t aOff[4], bOff[4];
#pragma unroll
    for (int mi = 0; mi < 4; mi++)
        aOff[mi] = (uint32_t)(wm * 64 + mi * 16 + (lane & 15)) * ROWB + (uint32_t)(lane >> 4) * 16;
#pragma unroll
    for (int pp = 0; pp < 4; pp++)
        bOff[pp] = (uint32_t)(wn * 64 + pp * 16 + ((lane >> 4) << 3) + (lane & 7)) * ROWB
                 + (uint32_t)(((lane >> 3) & 1) << 4);

    for (int kt = 0; kt < nK; kt++) {
        if (kt + 1 < nK)
            ld_stage(sbase + (uint32_t)((kt + 1) & 1) * STAGE_B,
                     Ahi, Alo, Bhi, Blo, m0, n0, M, Nmat, (kt + 1) * 32, tid);
        CP_COMMIT();
        CP_WAIT1();
        __syncthreads();

        uint32_t sb = sbase + (uint32_t)(kt & 1) * STAGE_B;
#pragma unroll
        for (int ks = 0; ks < 2; ks++) {
            uint32_t kb2 = (uint32_t)ks * 32;
            uint32_t bh[4][4], bl[4][4];
#pragma unroll
            for (int pp = 0; pp < 4; pp++) {
                ldsm_x4(bh[pp], sb + 2 * TILE_PAD + bOff[pp] + kb2);
                ldsm_x4(bl[pp], sb + 3 * TILE_PAD + bOff[pp] + kb2);
            }
#pragma unroll
            for (int mi = 0; mi < 4; mi++) {
                uint32_t ah[4], al[4];
                ldsm_x4(ah, sb + aOff[mi] + kb2);
                ldsm_x4(al, sb + TILE_PAD + aOff[mi] + kb2);
#pragma unroll
                for (int ni = 0; ni < 8; ni++)
                    mma16816(acc[mi][ni], ah, &bh[ni >> 1][(ni & 1) * 2]);
#pragma unroll
                for (int ni = 0; ni < 8; ni++)
                    mma16816(acc[mi][ni], ah, &bl[ni >> 1][(ni & 1) * 2]);
#pragma unroll
                for (int ni = 0; ni < 8; ni++)
                    mma16816(acc[mi][ni], al, &bh[ni >> 1][(ni & 1) * 2]);
            }
        }
        __syncthreads();
    }

    // epilogue
#pragma unroll
    for (int mi = 0; mi < 4; mi++) {
        int r0 = m0 + wm * 64 + mi * 16 + gID;
        int r1 = r0 + 8;
#pragma unroll
        for (int ni = 0; ni < 8; ni++) {
            int cbase = n0 + wn * 64 + ni * 8 + tg * 2;
            if (cbase >= Nmat) continue;
            bool two = (cbase + 1 < Nmat);
            float bx = bias ? bias[cbase] : 0.f;
            float by = (bias && two) ? bias[cbase + 1] : 0.f;
            if (r0 < M) {
                float* p = C + (size_t)r0 * Nmat + cbase;
                if (two) { p[0] = acc[mi][ni][0] + bx; p[1] = acc[mi][ni][1] + by; }
                else p[0] = acc[mi][ni][0] + bx;
            }
            if (r1 < M) {
                float* p = C + (size_t)r1 * Nmat + cbase;
                if (two) { p[0] = acc[mi][ni][2] + bx; p[1] = acc[mi][ni][3] + by; }
                else p[0] = acc[mi][ni][2] + bx;
            }
        }
    }
}

// ---------------- zero scratch ----------------
__global__ void k_zero() {
    size_t i = (size_t)blockIdx.x * blockDim.x + threadIdx.x;
    if (i < (size_t)Nn * NH * HIDF) g_acc1[i] = 0.f;
    if (i < (size_t)Nn * NH * OUTF) g_acc2[i] = 0.f;
    if (i < Nn * NH) {
        g_mkey1[i] = 0u; g_den1[i] = 0.f;
        g_mkey2[i] = 0u; g_den2[i] = 0.f;
    }
    if (i < INF_) { g_bnsum[i] = 0.f; g_bnsum2[i] = 0.f; }
    if (i < NDOMc * INF_) { g_dsum[i] = 0.f; g_dsum2[i] = 0.f; }
    if (i < NDOMc) g_cnt[i] = 0.f;
}

// ---------------- tiled SGEMM (GAT2 small GEMM) ----------------
#define BM 128
#define BN 128
#define BK 8
#define TM 8
#define TN 8
__global__ __launch_bounds__(256) void sgemm_k(
    const float* __restrict__ A, const float* __restrict__ B,
    const float* __restrict__ bias, float* __restrict__ C,
    int M, int Nc, int K)
{
    __shared__ float As[BK][BM];
    __shared__ float Bs[BK][BN];
    int tid = threadIdx.x;
    int m0 = blockIdx.y * BM;
    int n0 = blockIdx.x * BN;
    int tx = tid & 15, ty = tid >> 4;

    float acc[TM][TN];
    #pragma unroll
    for (int i = 0; i < TM; i++)
        #pragma unroll
        for (int j = 0; j < TN; j++) acc[i][j] = 0.f;

    int aRow = tid >> 1;
    int aCol = (tid & 1) * 4;
    int bRow = tid >> 5;
    int bCol = (tid & 31) * 4;

    int nK = K / BK;
    for (int kt = 0; kt < nK; kt++) {
        int kb = kt * BK;
        float4 av = make_float4(0.f, 0.f, 0.f, 0.f);
        if (m0 + aRow < M)
            av = *reinterpret_cast<const float4*>(A + (size_t)(m0 + aRow) * K + kb + aCol);
        As[aCol + 0][aRow] = av.x; As[aCol + 1][aRow] = av.y;
        As[aCol + 2][aRow] = av.z; As[aCol + 3][aRow] = av.w;

        const float* Bp = B + (size_t)(kb + bRow) * Nc + n0 + bCol;
        float4 bv;
        if (n0 + bCol + 3 < Nc && ((((size_t)Bp) & 15) == 0)) {
            bv = *reinterpret_cast<const float4*>(Bp);
        } else {
            bv.x = (n0 + bCol + 0 < Nc) ? Bp[0] : 0.f;
            bv.y = (n0 + bCol + 1 < Nc) ? Bp[1] : 0.f;
            bv.z = (n0 + bCol + 2 < Nc) ? Bp[2] : 0.f;
            bv.w = (n0 + bCol + 3 < Nc) ? Bp[3] : 0.f;
        }
        Bs[bRow][bCol + 0] = bv.x; Bs[bRow][bCol + 1] = bv.y;
        Bs[bRow][bCol + 2] = bv.z; Bs[bRow][bCol + 3] = bv.w;
        __syncthreads();

        #pragma unroll
        for (int k = 0; k < BK; k++) {
            float ar[TM], br[TN];
            #pragma unroll
            for (int i = 0; i < TM; i++) ar[i] = As[k][ty * TM + i];
            #pragma unroll
            for (int j = 0; j < TN; j++) br[j] = Bs[k][tx * TN + j];
            #pragma unroll
            for (int i = 0; i < TM; i++)
                #pragma unroll
                for (int j = 0; j < TN; j++) acc[i][j] += ar[i] * br[j];
        }
        __syncthreads();
    }

    #pragma unroll
    for (int i = 0; i < TM; i++) {
        int m = m0 + ty * TM + i;
        if (m >= M) continue;
        #pragma unroll
        for (int j = 0; j < TN; j++) {
            int n = n0 + tx * TN + j;
            if (n >= Nc) continue;
            float v = acc[i][j];
            if (bias) v += bias[n];
            C[(size_t)m * Nc + n] = v;
        }
    }
}

// ---------------- batch-norm column sums ----------------
__global__ void k_colsum(const float* __restrict__ X) {
    int j = blockIdx.x * blockDim.x + threadIdx.x;
    if (j >= INF_) return;
    int chunk = (Nn + gridDim.y - 1) / gridDim.y;
    int n0 = blockIdx.y * chunk;
    int n1 = min(n0 + chunk, Nn);
    float a = 0.f, b = 0.f;
    for (int n = n0; n < n1; n++) {
        float v = X[(size_t)n * INF_ + j];
        a += v; b += v * v;
    }
    atomicAdd(&g_bnsum[j], a);
    atomicAdd(&g_bnsum2[j], b);
}

__global__ void k_bn_elu(float* X, const float* __restrict__ g, const float* __restrict__ b) {
    size_t i = (size_t)blockIdx.x * blockDim.x + threadIdx.x;
    if (i >= (size_t)Nn * INF_) return;
    int j = (int)(i % INF_);
    float mu  = g_bnsum[j] * (1.f / Nn);
    float var = fmaxf(g_bnsum2[j] * (1.f / Nn) - mu * mu, 0.f);
    float xn = (X[i] - mu) * rsqrtf(var + EPSBN) * g[j] + b[j];
    X[i] = eluf(xn);
}

// ---------------- attention logits: warp per (n, h) ----------------
__global__ void k_attn_logits(const float* __restrict__ Hh, const float* __restrict__ asrc,
                              const float* __restrict__ adst, float* als, float* ald, int F) {
    int w = (int)(((size_t)blockIdx.x * blockDim.x + threadIdx.x) >> 5);
    int lane = threadIdx.x & 31;
    if (w >= Nn * NH) return;
    int h = w % NH;
    const float* hp = Hh + (size_t)w * F;
    float s = 0.f, d = 0.f;
    for (int t = lane; t < F; t += 32) {
        float hv = hp[t];
        s += hv * asrc[h * F + t];
        d += hv * adst[h * F + t];
    }
    #pragma unroll
    for (int o = 16; o; o >>= 1) {
        s += __shfl_down_sync(0xffffffffu, s, o);
        d += __shfl_down_sync(0xffffffffu, d, o);
    }
    if (lane == 0) { als[w] = s; ald[w] = d; }
}

// ---------------- edge softmax ----------------
__global__ void k_edge_max(const int* __restrict__ src, const int* __restrict__ dst,
                           const float* __restrict__ als, const float* __restrict__ ald,
                           float* e, unsigned* mkey) {
    int i = blockIdx.x * blockDim.x + threadIdx.x;
    if (i >= Ee * NH) return;
    int ed = i / NH, h = i % NH;
    float v = als[src[ed] * NH + h] + ald[dst[ed] * NH + h];
    v = v > 0.f ? v : 0.2f * v;
    e[i] = v;
    atomicMax(&mkey[dst[ed] * NH + h], f2o(v));
}

__global__ void k_edge_exp(const int* __restrict__ dst, float* e,
                           const unsigned* __restrict__ mkey, float* den) {
    int i = blockIdx.x * blockDim.x + threadIdx.x;
    if (i >= Ee * NH) return;
    int ed = i / NH, h = i % NH;
    float m = o2f(mkey[dst[ed] * NH + h]);
    float ex = expf(e[i] - m);
    e[i] = ex;
    atomicAdd(&den[dst[ed] * NH + h], ex);
}

// ---------------- weighted message scatter: block per edge ----------------
__global__ void k_scatter(const int* __restrict__ src, const int* __restrict__ dst,
                          const float* __restrict__ Hh, const float* __restrict__ e,
                          const float* __restrict__ den, float* out, int F) {
    int ed = blockIdx.x;
    int s = src[ed], d = dst[ed];
    __shared__ float alpha[NH];
    if (threadIdx.x < NH)
        alpha[threadIdx.x] = e[ed * NH + threadIdx.x] / (den[d * NH + threadIdx.x] + 1e-16f);
    __syncthreads();
    int tot = NH * F;
    for (int idx = threadIdx.x; idx < tot; idx += blockDim.x) {
        int h = idx / F;
        atomicAdd(&out[(size_t)d * tot + idx], Hh[(size_t)s * tot + idx] * alpha[h]);
    }
}

// ---------------- head mean (+ optional ELU) ----------------
__global__ void k_mean(const float* __restrict__ acc, float* out, int F, int doElu) {
    size_t i = (size_t)blockIdx.x * blockDim.x + threadIdx.x;
    if (i >= (size_t)Nn * F) return;
    int n = (int)(i / F), d2 = (int)(i % F);
    const float* p = acc + (size_t)n * NH * F + d2;
    float v = (p[0] + p[F] + p[2 * F]) * (1.f / NH);
    if (doElu) v = eluf(v);
    out[i] = v;
}

// ---------------- MLP head ----------------
__global__ void k_mlp(const float* __restrict__ z, const float* __restrict__ w1,
                      const float* __restrict__ b1, const float* __restrict__ w2,
                      const float* __restrict__ b2, const int* __restrict__ flag,
                      float* yp) {
    int n = blockIdx.x;
    int t = threadIdx.x; // 64 threads
    __shared__ float zs[OUTF];
    __shared__ float hid[MHc];
    if (t < OUTF) zs[t] = z[(size_t)n * OUTF + t];
    __syncthreads();
    if (*flag == 0) {
        if (t < NLABc) yp[(size_t)n * NLABc + t] = 0.f;
        return;
    }
    float a = b1[t];
    #pragma unroll
    for (int k = 0; k < OUTF; k++) a += zs[k] * w1[k * MHc + t];
    hid[t] = fmaxf(a, 0.f);
    __syncthreads();
    if (t < NLABc) {
        float o = b2[t];
        #pragma unroll
        for (int k2 = 0; k2 < MHc; k2++) o += hid[k2] * w2[k2 * NLABc + t];
        yp[(size_t)n * NLABc + t] = o;
    }
}

// ---------------- fc2 (K=30, memory-bound) ----------------
__global__ void k_fc2(const float* __restrict__ z, const float* __restrict__ W,
                      const float* __restrict__ b, float* out) {
    size_t i = (size_t)blockIdx.x * blockDim.x + threadIdx.x;
    if (i >= (size_t)Nn * INF_) return;
    int n = (int)(i / INF_), j = (int)(i % INF_);
    float acc = b[j];
    const float* zr = z + (size_t)n * OUTF;
    #pragma unroll
    for (int k = 0; k < OUTF; k++) acc += zr[k] * W[(size_t)k * INF_ + j];
    out[i] = acc;
}

// ---------------- DSBN ----------------
__global__ void k_cnt(const int* __restrict__ y) {
    int n = blockIdx.x * blockDim.x + threadIdx.x;
    if (n < Nn) atomicAdd(&g_cnt[y[n]], 1.f);
}

__global__ void k_dsbn_sum(const float* __restrict__ X, const int* __restrict__ y) {
    int j = blockIdx.x * blockDim.x + threadIdx.x;
    if (j >= INF_) return;
    int chunk = (Nn + gridDim.y - 1) / gridDim.y;
    int n0 = blockIdx.y * chunk;
    int n1 = min(n0 + chunk, Nn);
    float a[NDOMc], b[NDOMc];
    #pragma unroll
    for (int k = 0; k < NDOMc; k++) { a[k] = 0.f; b[k] = 0.f; }
    for (int n = n0; n < n1; n++) {
        int d = y[n];
        float v = X[(size_t)n * INF_ + j];
        #pragma unroll
        for (int k = 0; k < NDOMc; k++) {
            float m = (d == k) ? 1.f : 0.f;
            a[k] += m * v;
            b[k] += m * v * v;
        }
    }
    #pragma unroll
    for (int k = 0; k < NDOMc; k++) {
        atomicAdd(&g_dsum[k * INF_ + j], a[k]);
        atomicAdd(&g_dsum2[k * INF_ + j], b[k]);
    }
}

__global__ void k_dsbn_elu(float* X, const int* __restrict__ y,
                           const float* __restrict__ gmm, const float* __restrict__ bta) {
    size_t i = (size_t)blockIdx.x * blockDim.x + threadIdx.x;
    if (i >= (size_t)Nn * INF_) return;
    int n = (int)(i / INF_), j = (int)(i % INF_);
    int d = y[n];
    float c = g_cnt[d];
    float x = X[i];
    float o = x;
    if (c > 1.f) {
        float mu  = g_dsum[d * INF_ + j] / c;
        float var = fmaxf(g_dsum2[d * INF_ + j] / c - mu * mu, 0.f);
        o = (x - mu) * rsqrtf(var + EPSBN) * gmm[d * INF_ + j] + bta[d * INF_ + j];
    }
    X[i] = eluf(o);
}

// ======================================================================
extern "C" void kernel_launch(void* const* d_in, const int* in_sizes, int n_in,
                              void* d_out, int out_size) {
    const float* features = (const float*)d_in[0];
    const int*   ei       = (const int*)d_in[1];
    const int*   y        = (const int*)d_in[2];
    const int*   flag     = (const int*)d_in[3];
    const float* fc1_w    = (const float*)d_in[4];
    const float* fc1_b    = (const float*)d_in[5];
    const float* bn_g     = (const float*)d_in[6];
    const float* bn_b     = (const float*)d_in[7];
    const float* W1       = (const float*)d_in[8];
    const float* a1_src   = (const float*)d_in[9];
    const float* a1_dst   = (const float*)d_in[10];
    const float* W2       = (const float*)d_in[11];
    const float* a2_src   = (const float*)d_in[12];
    const float* a2_dst   = (const float*)d_in[13];
    const float* mlp_w1   = (const float*)d_in[14];
    const float* mlp_b1   = (const float*)d_in[15];
    const float* mlp_w2   = (const float*)d_in[16];
    const float* mlp_b2   = (const float*)d_in[17];
    const float* fc2_w    = (const float*)d_in[18];
    const float* fc2_b    = (const float*)d_in[19];
    const float* dsbn_g   = (const float*)d_in[20];
    const float* dsbn_b   = (const float*)d_in[21];
    const float* fc3_w    = (const float*)d_in[22];
    const float* fc3_b    = (const float*)d_in[23];

    float* out    = (float*)d_out;
    float* z_out  = out;                                    // [N, 30]
    float* h3_out = out + (size_t)Nn * OUTF;                // [N, 3000]
    float* yp_out = h3_out + (size_t)Nn * INF_;             // [N, 20]
    const int* srcp = ei;
    const int* dstp = ei + Ee;

    void* p;
    cudaGetSymbolAddress(&p, g_x);     float* px    = (float*)p;
    cudaGetSymbolAddress(&p, g_H);     float* pH    = (float*)p;
    cudaGetSymbolAddress(&p, g_acc1);  float* pacc1 = (float*)p;
    cudaGetSymbolAddress(&p, g_h1);    float* ph1   = (float*)p;
    cudaGetSymbolAddress(&p, g_H2);    float* pH2   = (float*)p;
    cudaGetSymbolAddress(&p, g_acc2);  float* pacc2 = (float*)p;
    cudaGetSymbolAddress(&p, g_als1);  float* pals1 = (float*)p;
    cudaGetSymbolAddress(&p, g_ald1);  float* pald1 = (float*)p;
    cudaGetSymbolAddress(&p, g_als2);  float* pals2 = (float*)p;
    cudaGetSymbolAddress(&p, g_ald2);  float* pald2 = (float*)p;
    cudaGetSymbolAddress(&p, g_e1);    float* pe1   = (float*)p;
    cudaGetSymbolAddress(&p, g_e2);    float* pe2   = (float*)p;
    cudaGetSymbolAddress(&p, g_mkey1); unsigned* pmk1 = (unsigned*)p;
    cudaGetSymbolAddress(&p, g_mkey2); unsigned* pmk2 = (unsigned*)p;
    cudaGetSymbolAddress(&p, g_den1);  float* pden1 = (float*)p;
    cudaGetSymbolAddress(&p, g_den2);  float* pden2 = (float*)p;
    cudaGetSymbolAddress(&p, g_Ahi);   __nv_bfloat16* pAhi = (__nv_bfloat16*)p;
    cudaGetSymbolAddress(&p, g_Alo);   __nv_bfloat16* pAlo = (__nv_bfloat16*)p;
    cudaGetSymbolAddress(&p, g_Whi);   __nv_bfloat16* pWhi = (__nv_bfloat16*)p;
    cudaGetSymbolAddress(&p, g_Wlo);   __nv_bfloat16* pWlo = (__nv_bfloat16*)p;

    static int smem_set = 0;
    if (!smem_set) {
        cudaFuncSetAttribute(gemm_mma3, cudaFuncAttributeMaxDynamicSharedMemorySize, GSMEM);
        smem_set = 1;
    }

    const int nMt = (Nn + 127) / 128;   // 157
    const size_t splitGrid4 = ((size_t)Nn * (KPAD / 4) + 255) / 256;

    // 0) zero scratch
    {
        size_t tot = (size_t)Nn * NH * HIDF;
        k_zero<<<(unsigned)((tot + 255) / 256), 256>>>();
    }

    // 1) fc1: x = features @ fc1_w + fc1_b
    {
        dim3 tg((KPAD + 31) / 32, (INF_ + 31) / 32);
        k_splitWT<<<tg, dim3(32, 32)>>>(fc1_w, pWhi, pWlo, INF_, INF_);
        k_splitA4<<<(unsigned)splitGrid4, 256>>>(features, pAhi, pAlo, Nn, INF_);
        int nNt = (INF_ + 127) / 128;   // 24
        gemm_mma3<<<nMt * nNt, 128, GSMEM>>>(pAhi, pAlo, pWhi, pWlo, fc1_b, px, Nn, INF_, nNt);
    }

    // 2) batchnorm + ELU (in place)
    {
        dim3 grid((INF_ + 255) / 256, 64);
        k_colsum<<<grid, 256>>>(px);
        size_t tot = (size_t)Nn * INF_;
        k_bn_elu<<<(unsigned)((tot + 255) / 256), 256>>>(px, bn_g, bn_b);
    }

    // 3) GAT layer 1
    {
        dim3 tg((KPAD + 31) / 32, (NH * HIDF + 31) / 32);
        k_splitWT<<<tg, dim3(32, 32)>>>(W1, pWhi, pWlo, INF_, NH * HIDF);
        k_splitA4<<<(unsigned)splitGrid4, 256>>>(px, pAhi, pAlo, Nn, INF_);
        int nNt = (NH * HIDF + 127) / 128;  // 12
        gemm_mma3<<<nMt * nNt, 128, GSMEM>>>(pAhi, pAlo, pWhi, pWlo, nullptr, pH, Nn, NH * HIDF, nNt);

        int warps = Nn * NH;
        k_attn_logits<<<(warps * 32 + 127) / 128, 128>>>(pH, a1_src, a1_dst, pals1, pald1, HIDF);

        int et = Ee * NH;
        k_edge_max<<<(et + 255) / 256, 256>>>(srcp, dstp, pals1, pald1, pe1, pmk1);
        k_edge_exp<<<(et + 255) / 256, 256>>>(dstp, pe1, pmk1, pden1);
        k_scatter<<<Ee, 256>>>(srcp, dstp, pH, pe1, pden1, pacc1, HIDF);

        size_t tot = (size_t)Nn * HIDF;
        k_mean<<<(unsigned)((tot + 255) / 256), 256>>>(pacc1, ph1, HIDF, 1);
    }

    // 4) GAT layer 2 -> z
    {
        dim3 grid((NH * OUTF + BN - 1) / BN, (Nn + BM - 1) / BM);
        sgemm_k<<<grid, 256>>>(ph1, W2, nullptr, pH2, Nn, NH * OUTF, HIDF);

        int warps = Nn * NH;
        k_attn_logits<<<(warps * 32 + 127) / 128, 128>>>(pH2, a2_src, a2_dst, pals2, pald2, OUTF);

        int et = Ee * NH;
        k_edge_max<<<(et + 255) / 256, 256>>>(srcp, dstp, pals2, pald2, pe2, pmk2);
        k_edge_exp<<<(et + 255) / 256, 256>>>(dstp, pe2, pmk2, pden2);
        k_scatter<<<Ee, 128>>>(srcp, dstp, pH2, pe2, pden2, pacc2, OUTF);

        size_t tot = (size_t)Nn * OUTF;
        k_mean<<<(unsigned)((tot + 255) / 256), 256>>>(pacc2, z_out, OUTF, 0);
    }

    // 5) MLP head -> y_pred
    k_mlp<<<Nn, MHc>>>(z_out, mlp_w1, mlp_b1, mlp_w2, mlp_b2, flag, yp_out);

    // 6) fc2 -> DSBN -> ELU (reuse g_x)
    {
        size_t tot = (size_t)Nn * INF_;
        k_fc2<<<(unsigned)((tot + 255) / 256), 256>>>(z_out, fc2_w, fc2_b, px);
        k_cnt<<<(Nn + 255) / 256, 256>>>(y);
        dim3 grid((INF_ + 255) / 256, 64);
        k_dsbn_sum<<<grid, 256>>>(px, y);
        k_dsbn_elu<<<(unsigned)((tot + 255) / 256), 256>>>(px, y, dsbn_g, dsbn_b);
    }

    // 7) fc3 -> h3
    {
        dim3 tg((KPAD + 31) / 32, (INF_ + 31) / 32);
        k_splitWT<<<tg, dim3(32, 32)>>>(fc3_w, pWhi, pWlo, INF_, INF_);
        k_splitA4<<<(unsigned)splitGrid4, 256>>>(px, pAhi, pAlo, Nn, INF_);
        int nNt = (INF_ + 127) / 128;   // 24
        gemm_mma3<<<nMt * nNt, 128, GSMEM>>>(pAhi, pAlo, pWhi, pWlo, fc3_b, h3_out, Nn, INF_, nNt);
    }
}

// round 9
// speedup vs baseline: 1.1031x; 1.1031x over previous
#include <cuda_runtime.h>
#include <cuda_bf16.h>
#include <math.h>
#include <stdint.h>

#define Nn    20000
#define Ee    120000
#define INF_  3000
#define HIDF  512
#define OUTF  30
#define NH    3
#define NDOMc 4
#define MHc   64
#define NLABc 20
#define EPSBN 1e-5f
#define KPAD  3008                 // 3000 padded to multiple of 32

// ---------------- scratch (static device memory; no allocations) ----------------
__device__ float    g_x[(size_t)Nn * INF_];
__device__ float    g_H[(size_t)Nn * NH * HIDF];
__device__ float    g_acc1[(size_t)Nn * NH * HIDF];
__device__ float    g_h1[(size_t)Nn * HIDF];
__device__ float    g_H2[(size_t)Nn * NH * OUTF];
__device__ float    g_acc2[(size_t)Nn * NH * OUTF];
__device__ float    g_als1[Nn * NH], g_ald1[Nn * NH];
__device__ float    g_als2[Nn * NH], g_ald2[Nn * NH];
__device__ float    g_e1[(size_t)Ee * NH];
__device__ float    g_e2[(size_t)Ee * NH];
__device__ unsigned g_mkey1[Nn * NH], g_mkey2[Nn * NH];
__device__ float    g_den1[Nn * NH], g_den2[Nn * NH];
__device__ float    g_bnsum[INF_], g_bnsum2[INF_];
__device__ float    g_dsum[NDOMc * INF_], g_dsum2[NDOMc * INF_];
__device__ float    g_cnt[NDOMc];
__device__ __align__(256) __nv_bfloat16 g_Ahi[(size_t)Nn * KPAD];
__device__ __align__(256) __nv_bfloat16 g_Alo[(size_t)Nn * KPAD];
__device__ __align__(256) __nv_bfloat16 g_Whi[(size_t)INF_ * KPAD];
__device__ __align__(256) __nv_bfloat16 g_Wlo[(size_t)INF_ * KPAD];

// ---------------- helpers ----------------
__device__ __forceinline__ unsigned f2o(float f) {
    unsigned u = __float_as_uint(f);
    return (u & 0x80000000u) ? ~u : (u | 0x80000000u);
}
__device__ __forceinline__ float o2f(unsigned k) {
    return (k & 0x80000000u) ? __uint_as_float(k ^ 0x80000000u) : __uint_as_float(~k);
}
__device__ __forceinline__ float eluf(float v) { return v > 0.f ? v : (expf(v) - 1.f); }

__device__ __forceinline__ uint32_t smem_u32(const void* p) {
    uint32_t a;
    asm("{ .reg .u64 t; cvta.to.shared.u64 t, %1; cvt.u32.u64 %0, t; }" : "=r"(a) : "l"(p));
    return a;
}

__device__ __forceinline__ void cp16(uint32_t dst, const void* src, int ok) {
    asm volatile("cp.async.cg.shared.global [%0], [%1], 16, %2;"
                 :: "r"(dst), "l"(src), "r"(ok ? 16 : 0) : "memory");
}
#define CP_COMMIT() asm volatile("cp.async.commit_group;" ::: "memory")
#define CP_WAIT1()  asm volatile("cp.async.wait_group 1;" ::: "memory")

__device__ __forceinline__ void mma16816(float* c, const uint32_t* a, const uint32_t* b) {
    asm volatile(
        "mma.sync.aligned.m16n8k16.row.col.f32.bf16.bf16.f32 "
        "{%0,%1,%2,%3},{%4,%5,%6,%7},{%8,%9},{%0,%1,%2,%3};"
        : "+f"(c[0]), "+f"(c[1]), "+f"(c[2]), "+f"(c[3])
        : "r"(a[0]), "r"(a[1]), "r"(a[2]), "r"(a[3]), "r"(b[0]), "r"(b[1]));
}
__device__ __forceinline__ void ldsm_x4(uint32_t* r, uint32_t addr) {
    asm volatile("ldmatrix.sync.aligned.m8n8.x4.shared.b16 {%0,%1,%2,%3}, [%4];"
                 : "=r"(r[0]), "=r"(r[1]), "=r"(r[2]), "=r"(r[3]) : "r"(addr));
}

// ---------------- split helpers ----------------
__device__ __forceinline__ void split_store4(__nv_bfloat16* hi, __nv_bfloat16* lo, size_t o,
                                             float v0, float v1, float v2, float v3) {
    __nv_bfloat16 h0 = __float2bfloat16(v0), h1 = __float2bfloat16(v1);
    __nv_bfloat16 h2 = __float2bfloat16(v2), h3 = __float2bfloat16(v3);
    __nv_bfloat162 hp0 = __nv_bfloat162(h0, h1), hp1 = __nv_bfloat162(h2, h3);
    __nv_bfloat162 lp0 = __nv_bfloat162(__float2bfloat16(v0 - __bfloat162float(h0)),
                                        __float2bfloat16(v1 - __bfloat162float(h1)));
    __nv_bfloat162 lp1 = __nv_bfloat162(__float2bfloat16(v2 - __bfloat162float(h2)),
                                        __float2bfloat16(v3 - __bfloat162float(h3)));
    uint2 hv, lv;
    hv.x = *(uint32_t*)&hp0; hv.y = *(uint32_t*)&hp1;
    lv.x = *(uint32_t*)&lp0; lv.y = *(uint32_t*)&lp1;
    *reinterpret_cast<uint2*>(hi + o) = hv;
    *reinterpret_cast<uint2*>(lo + o) = lv;
}

__global__ void k_splitA4(const float* __restrict__ X, __nv_bfloat16* __restrict__ hi,
                          __nv_bfloat16* __restrict__ lo, int M, int K) {
    size_t i4 = (size_t)blockIdx.x * blockDim.x + threadIdx.x;
    const int kq = KPAD / 4;
    if (i4 >= (size_t)M * kq) return;
    int m = (int)(i4 / kq), k4 = (int)(i4 % kq) * 4;
    const float* row = X + (size_t)m * K;
    float v0, v1, v2, v3;
    if (k4 + 3 < K) {
        float4 f = *reinterpret_cast<const float4*>(row + k4);
        v0 = f.x; v1 = f.y; v2 = f.z; v3 = f.w;
    } else {
        v0 = (k4 + 0 < K) ? row[k4 + 0] : 0.f;
        v1 = (k4 + 1 < K) ? row[k4 + 1] : 0.f;
        v2 = (k4 + 2 < K) ? row[k4 + 2] : 0.f;
        v3 = (k4 + 3 < K) ? row[k4 + 3] : 0.f;
    }
    split_store4(hi, lo, (size_t)m * KPAD + k4, v0, v1, v2, v3);
}

// Fused: BN apply + ELU + bf16 split (no intermediate h0 materialization)
__global__ void k_bn_elu_split(const float* __restrict__ X,
                               const float* __restrict__ g, const float* __restrict__ b,
                               __nv_bfloat16* __restrict__ hi, __nv_bfloat16* __restrict__ lo) {
    size_t i4 = (size_t)blockIdx.x * blockDim.x + threadIdx.x;
    const int kq = KPAD / 4;
    if (i4 >= (size_t)Nn * kq) return;
    int m = (int)(i4 / kq), k4 = (int)(i4 % kq) * 4;
    float v[4];
    if (k4 + 3 < INF_) {
        float4 f = *reinterpret_cast<const float4*>(X + (size_t)m * INF_ + k4);
        v[0] = f.x; v[1] = f.y; v[2] = f.z; v[3] = f.w;
#pragma unroll
        for (int q = 0; q < 4; q++) {
            int j = k4 + q;
            float mu  = g_bnsum[j] * (1.f / Nn);
            float var = fmaxf(g_bnsum2[j] * (1.f / Nn) - mu * mu, 0.f);
            v[q] = eluf((v[q] - mu) * rsqrtf(var + EPSBN) * g[j] + b[j]);
        }
    } else {
#pragma unroll
        for (int q = 0; q < 4; q++) {
            int j = k4 + q;
            if (j < INF_) {
                float x = X[(size_t)m * INF_ + j];
                float mu  = g_bnsum[j] * (1.f / Nn);
                float var = fmaxf(g_bnsum2[j] * (1.f / Nn) - mu * mu, 0.f);
                v[q] = eluf((x - mu) * rsqrtf(var + EPSBN) * g[j] + b[j]);
            } else v[q] = 0.f;
        }
    }
    split_store4(hi, lo, (size_t)m * KPAD + k4, v[0], v[1], v[2], v[3]);
}

// Fused: DSBN apply + ELU + bf16 split
__global__ void k_dsbn_elu_split(const float* __restrict__ X, const int* __restrict__ y,
                                 const float* __restrict__ gmm, const float* __restrict__ bta,
                                 __nv_bfloat16* __restrict__ hi, __nv_bfloat16* __restrict__ lo) {
    size_t i4 = (size_t)blockIdx.x * blockDim.x + threadIdx.x;
    const int kq = KPAD / 4;
    if (i4 >= (size_t)Nn * kq) return;
    int m = (int)(i4 / kq), k4 = (int)(i4 % kq) * 4;
    int d = y[m];
    float c = g_cnt[d];
    bool norm = (c > 1.f);
    float inv = norm ? (1.f / c) : 0.f;
    float v[4];
#pragma unroll
    for (int q = 0; q < 4; q++) {
        int j = k4 + q;
        if (j < INF_) {
            float x = X[(size_t)m * INF_ + j];
            float o = x;
            if (norm) {
                float mu  = g_dsum[d * INF_ + j] * inv;
                float var = fmaxf(g_dsum2[d * INF_ + j] * inv - mu * mu, 0.f);
                o = (x - mu) * rsqrtf(var + EPSBN) * gmm[d * INF_ + j] + bta[d * INF_ + j];
            }
            v[q] = eluf(o);
        } else v[q] = 0.f;
    }
    split_store4(hi, lo, (size_t)m * KPAD + k4, v[0], v[1], v[2], v[3]);
}

// W[K, N] f32 -> WT hi/lo [N, KPAD] bf16 (zero pad beyond K)
__global__ void k_splitWT(const float* __restrict__ W, __nv_bfloat16* __restrict__ hi,
                          __nv_bfloat16* __restrict__ lo, int K, int Nmat) {
    __shared__ float t[32][33];
    int kb = blockIdx.x * 32, nb = blockIdx.y * 32;
    int rk = kb + threadIdx.y, rn = nb + threadIdx.x;
    t[threadIdx.y][threadIdx.x] = (rk < K && rn < Nmat) ? W[(size_t)rk * Nmat + rn] : 0.f;
    __syncthreads();
    int wn = nb + threadIdx.y, wk = kb + threadIdx.x;
    if (wn < Nmat && wk < KPAD) {
        float x = t[threadIdx.x][threadIdx.y];
        __nv_bfloat16 h = __float2bfloat16(x);
        size_t o = (size_t)wn * KPAD + wk;
        hi[o] = h;
        lo[o] = __float2bfloat16(x - __bfloat162float(h));
    }
}

// ---------------- mma.sync bf16x3 GEMM, 256 thr, ldmatrix, 2 CTAs/SM (round-6 best) ----
#define ROWB      80
#define TILE_PAD  (128 * ROWB)
#define STAGE_B   (4 * TILE_PAD)
#define GSMEM     (2 * STAGE_B)

__device__ __forceinline__ void ld_stage(
    uint32_t sb,
    const __nv_bfloat16* __restrict__ Ahi, const __nv_bfloat16* __restrict__ Alo,
    const __nv_bfloat16* __restrict__ Bhi, const __nv_bfloat16* __restrict__ Blo,
    int m0, int n0, int M, int Nmat, int kb, int tid)
{
    int tile = tid >> 6;
    int r0 = (tid & 63) * 2;
    const __nv_bfloat16* base;
    int lim, off;
    if (tile < 2) { base = (tile == 0) ? Ahi : Alo; lim = M;    off = m0; }
    else          { base = (tile == 2) ? Bhi : Blo; lim = Nmat; off = n0; }
#pragma unroll
    for (int rr = 0; rr < 2; rr++) {
        int row = r0 + rr;
        int grow = off + row;
        int ok = grow < lim;
        const __nv_bfloat16* g = base + (size_t)(ok ? grow : 0) * KPAD + kb;
        uint32_t so = sb + (uint32_t)tile * TILE_PAD + (uint32_t)row * ROWB;
        cp16(so,      g,      ok);
        cp16(so + 16, g + 8,  ok);
        cp16(so + 32, g + 16, ok);
        cp16(so + 48, g + 24, ok);
    }
}

__global__ void __launch_bounds__(256, 2) gemm_mma3(
    const __nv_bfloat16* __restrict__ Ahi, const __nv_bfloat16* __restrict__ Alo,
    const __nv_bfloat16* __restrict__ Bhi, const __nv_bfloat16* __restrict__ Blo,
    const float* __restrict__ bias, float* __restrict__ C,
    int M, int Nmat, int nNt)
{
    extern __shared__ char smem[];
    uint32_t sbase = smem_u32(smem);
    int tid = threadIdx.x, lane = tid & 31, wid = tid >> 5;
    int wm = wid >> 2, wn = wid & 3;
    int gID = lane >> 2, tg = lane & 3;
    int bid = blockIdx.x;
    int nt = bid % nNt, mt = bid / nNt;
    int m0 = mt * 128, n0 = nt * 128;
    const int nK = KPAD / 32;

    float acc[4][4][4];
#pragma unroll
    for (int i = 0; i < 4; i++)
#pragma unroll
        for (int j = 0; j < 4; j++)
#pragma unroll
            for (int q = 0; q < 4; q++) acc[i][j][q] = 0.f;

    ld_stage(sbase, Ahi, Alo, Bhi, Blo, m0, n0, M, Nmat, 0, tid);
    CP_COMMIT();

    uint32_t aOff[4], bOff[2];
#pragma unroll
    for (int mi = 0; mi < 4; mi++)
        aOff[mi] = (uint32_t)(wm * 64 + mi * 16 + (lane & 15)) * ROWB + (uint32_t)(lane >> 4) * 16;
#pragma unroll
    for (int pp = 0; pp < 2; pp++)
        bOff[pp] = (uint32_t)(wn * 32 + pp * 16 + ((lane >> 4) << 3) + (lane & 7)) * ROWB
                 + (uint32_t)(((lane >> 3) & 1) << 4);

    for (int kt = 0; kt < nK; kt++) {
        if (kt + 1 < nK)
            ld_stage(sbase + (uint32_t)((kt + 1) & 1) * STAGE_B,
                     Ahi, Alo, Bhi, Blo, m0, n0, M, Nmat, (kt + 1) * 32, tid);
        CP_COMMIT();
        CP_WAIT1();
        __syncthreads();

        uint32_t sb = sbase + (uint32_t)(kt & 1) * STAGE_B;
#pragma unroll
        for (int ks = 0; ks < 2; ks++) {
            uint32_t kb2 = (uint32_t)ks * 32;
            uint32_t bh[2][4], bl[2][4];
#pragma unroll
            for (int pp = 0; pp < 2; pp++) {
                ldsm_x4(bh[pp], sb + 2 * TILE_PAD + bOff[pp] + kb2);
                ldsm_x4(bl[pp], sb + 3 * TILE_PAD + bOff[pp] + kb2);
            }
#pragma unroll
            for (int mi = 0; mi < 4; mi++) {
                uint32_t ah[4], al[4];
                ldsm_x4(ah, sb + aOff[mi] + kb2);
                ldsm_x4(al, sb + TILE_PAD + aOff[mi] + kb2);
#pragma unroll
                for (int ni = 0; ni < 4; ni++) {
                    uint32_t* Bh = &bh[ni >> 1][(ni & 1) * 2];
                    uint32_t* Bl = &bl[ni >> 1][(ni & 1) * 2];
                    mma16816(acc[mi][ni], ah, Bh);
                    mma16816(acc[mi][ni], ah, Bl);
                    mma16816(acc[mi][ni], al, Bh);
                }
            }
        }
        __syncthreads();
    }

#pragma unroll
    for (int mi = 0; mi < 4; mi++) {
        int r0 = m0 + wm * 64 + mi * 16 + gID;
        int r1 = r0 + 8;
#pragma unroll
        for (int ni = 0; ni < 4; ni++) {
            int cbase = n0 + wn * 32 + ni * 8 + tg * 2;
            if (cbase >= Nmat) continue;
            bool two = (cbase + 1 < Nmat);
            float bx = bias ? bias[cbase] : 0.f;
            float by = (bias && two) ? bias[cbase + 1] : 0.f;
            if (r0 < M) {
                float* p = C + (size_t)r0 * Nmat + cbase;
                if (two) { p[0] = acc[mi][ni][0] + bx; p[1] = acc[mi][ni][1] + by; }
                else p[0] = acc[mi][ni][0] + bx;
            }
            if (r1 < M) {
                float* p = C + (size_t)r1 * Nmat + cbase;
                if (two) { p[0] = acc[mi][ni][2] + bx; p[1] = acc[mi][ni][3] + by; }
                else p[0] = acc[mi][ni][2] + bx;
            }
        }
    }
}

// ---------------- zero scratch ----------------
__global__ void k_zero() {
    size_t i = (size_t)blockIdx.x * blockDim.x + threadIdx.x;
    if (i < (size_t)Nn * NH * HIDF) g_acc1[i] = 0.f;
    if (i < (size_t)Nn * NH * OUTF) g_acc2[i] = 0.f;
    if (i < Nn * NH) {
        g_mkey1[i] = 0u; g_den1[i] = 0.f;
        g_mkey2[i] = 0u; g_den2[i] = 0.f;
    }
    if (i < INF_) { g_bnsum[i] = 0.f; g_bnsum2[i] = 0.f; }
    if (i < NDOMc * INF_) { g_dsum[i] = 0.f; g_dsum2[i] = 0.f; }
    if (i < NDOMc) g_cnt[i] = 0.f;
}

// ---------------- tiled SGEMM (GAT2 small GEMM) ----------------
#define BM 128
#define BN 128
#define BK 8
#define TM 8
#define TN 8
__global__ __launch_bounds__(256) void sgemm_k(
    const float* __restrict__ A, const float* __restrict__ B,
    const float* __restrict__ bias, float* __restrict__ C,
    int M, int Nc, int K)
{
    __shared__ float As[BK][BM];
    __shared__ float Bs[BK][BN];
    int tid = threadIdx.x;
    int m0 = blockIdx.y * BM;
    int n0 = blockIdx.x * BN;
    int tx = tid & 15, ty = tid >> 4;

    float acc[TM][TN];
    #pragma unroll
    for (int i = 0; i < TM; i++)
        #pragma unroll
        for (int j = 0; j < TN; j++) acc[i][j] = 0.f;

    int aRow = tid >> 1;
    int aCol = (tid & 1) * 4;
    int bRow = tid >> 5;
    int bCol = (tid & 31) * 4;

    int nK = K / BK;
    for (int kt = 0; kt < nK; kt++) {
        int kb = kt * BK;
        float4 av = make_float4(0.f, 0.f, 0.f, 0.f);
        if (m0 + aRow < M)
            av = *reinterpret_cast<const float4*>(A + (size_t)(m0 + aRow) * K + kb + aCol);
        As[aCol + 0][aRow] = av.x; As[aCol + 1][aRow] = av.y;
        As[aCol + 2][aRow] = av.z; As[aCol + 3][aRow] = av.w;

        const float* Bp = B + (size_t)(kb + bRow) * Nc + n0 + bCol;
        float4 bv;
        if (n0 + bCol + 3 < Nc && ((((size_t)Bp) & 15) == 0)) {
            bv = *reinterpret_cast<const float4*>(Bp);
        } else {
            bv.x = (n0 + bCol + 0 < Nc) ? Bp[0] : 0.f;
            bv.y = (n0 + bCol + 1 < Nc) ? Bp[1] : 0.f;
            bv.z = (n0 + bCol + 2 < Nc) ? Bp[2] : 0.f;
            bv.w = (n0 + bCol + 3 < Nc) ? Bp[3] : 0.f;
        }
        Bs[bRow][bCol + 0] = bv.x; Bs[bRow][bCol + 1] = bv.y;
        Bs[bRow][bCol + 2] = bv.z; Bs[bRow][bCol + 3] = bv.w;
        __syncthreads();

        #pragma unroll
        for (int k = 0; k < BK; k++) {
            float ar[TM], br[TN];
            #pragma unroll
            for (int i = 0; i < TM; i++) ar[i] = As[k][ty * TM + i];
            #pragma unroll
            for (int j = 0; j < TN; j++) br[j] = Bs[k][tx * TN + j];
            #pragma unroll
            for (int i = 0; i < TM; i++)
                #pragma unroll
                for (int j = 0; j < TN; j++) acc[i][j] += ar[i] * br[j];
        }
        __syncthreads();
    }

    #pragma unroll
    for (int i = 0; i < TM; i++) {
        int m = m0 + ty * TM + i;
        if (m >= M) continue;
        #pragma unroll
        for (int j = 0; j < TN; j++) {
            int n = n0 + tx * TN + j;
            if (n >= Nc) continue;
            float v = acc[i][j];
            if (bias) v += bias[n];
            C[(size_t)m * Nc + n] = v;
        }
    }
}

// ---------------- batch-norm column sums ----------------
__global__ void k_colsum(const float* __restrict__ X) {
    int j = blockIdx.x * blockDim.x + threadIdx.x;
    if (j >= INF_) return;
    int chunk = (Nn + gridDim.y - 1) / gridDim.y;
    int n0 = blockIdx.y * chunk;
    int n1 = min(n0 + chunk, Nn);
    float a = 0.f, b = 0.f;
    for (int n = n0; n < n1; n++) {
        float v = X[(size_t)n * INF_ + j];
        a += v; b += v * v;
    }
    atomicAdd(&g_bnsum[j], a);
    atomicAdd(&g_bnsum2[j], b);
}

// ---------------- attention logits: warp per (n, h) ----------------
__global__ void k_attn_logits(const float* __restrict__ Hh, const float* __restrict__ asrc,
                              const float* __restrict__ adst, float* als, float* ald, int F) {
    int w = (int)(((size_t)blockIdx.x * blockDim.x + threadIdx.x) >> 5);
    int lane = threadIdx.x & 31;
    if (w >= Nn * NH) return;
    int h = w % NH;
    const float* hp = Hh + (size_t)w * F;
    float s = 0.f, d = 0.f;
    for (int t = lane; t < F; t += 32) {
        float hv = hp[t];
        s += hv * asrc[h * F + t];
        d += hv * adst[h * F + t];
    }
    #pragma unroll
    for (int o = 16; o; o >>= 1) {
        s += __shfl_down_sync(0xffffffffu, s, o);
        d += __shfl_down_sync(0xffffffffu, d, o);
    }
    if (lane == 0) { als[w] = s; ald[w] = d; }
}

// ---------------- edge softmax ----------------
__global__ void k_edge_max(const int* __restrict__ src, const int* __restrict__ dst,
                           const float* __restrict__ als, const float* __restrict__ ald,
                           float* e, unsigned* mkey) {
    int i = blockIdx.x * blockDim.x + threadIdx.x;
    if (i >= Ee * NH) return;
    int ed = i / NH, h = i % NH;
    float v = als[src[ed] * NH + h] + ald[dst[ed] * NH + h];
    v = v > 0.f ? v : 0.2f * v;
    e[i] = v;
    atomicMax(&mkey[dst[ed] * NH + h], f2o(v));
}

__global__ void k_edge_exp(const int* __restrict__ dst, float* e,
                           const unsigned* __restrict__ mkey, float* den) {
    int i = blockIdx.x * blockDim.x + threadIdx.x;
    if (i >= Ee * NH) return;
    int ed = i / NH, h = i % NH;
    float m = o2f(mkey[dst[ed] * NH + h]);
    float ex = expf(e[i] - m);
    e[i] = ex;
    atomicAdd(&den[dst[ed] * NH + h], ex);
}

// ---------------- weighted message scatter ----------------
// float4 variant (F % 128 == 0): GAT1
__global__ void k_scatter4(const int* __restrict__ src, const int* __restrict__ dst,
                           const float* __restrict__ Hh, const float* __restrict__ e,
                           const float* __restrict__ den, float* out, int F) {
    int ed = blockIdx.x;
    int s = src[ed], d = dst[ed];
    __shared__ float alpha[NH];
    if (threadIdx.x < NH)
        alpha[threadIdx.x] = e[ed * NH + threadIdx.x] / (den[d * NH + threadIdx.x] + 1e-16f);
    __syncthreads();
    int tot4 = NH * F / 4;
    int fq = F / 4;
    const float4* Hs = reinterpret_cast<const float4*>(Hh + (size_t)s * NH * F);
    float* od = out + (size_t)d * NH * F;
    for (int i4 = threadIdx.x; i4 < tot4; i4 += blockDim.x) {
        int h = i4 / fq;
        float a = alpha[h];
        float4 v = Hs[i4];
        int base = i4 * 4;
        atomicAdd(&od[base + 0], v.x * a);
        atomicAdd(&od[base + 1], v.y * a);
        atomicAdd(&od[base + 2], v.z * a);
        atomicAdd(&od[base + 3], v.w * a);
    }
}

__global__ void k_scatter(const int* __restrict__ src, const int* __restrict__ dst,
                          const float* __restrict__ Hh, const float* __restrict__ e,
                          const float* __restrict__ den, float* out, int F) {
    int ed = blockIdx.x;
    int s = src[ed], d = dst[ed];
    __shared__ float alpha[NH];
    if (threadIdx.x < NH)
        alpha[threadIdx.x] = e[ed * NH + threadIdx.x] / (den[d * NH + threadIdx.x] + 1e-16f);
    __syncthreads();
    int tot = NH * F;
    for (int idx = threadIdx.x; idx < tot; idx += blockDim.x) {
        int h = idx / F;
        atomicAdd(&out[(size_t)d * tot + idx], Hh[(size_t)s * tot + idx] * alpha[h]);
    }
}

// ---------------- head mean (+ optional ELU) ----------------
__global__ void k_mean(const float* __restrict__ acc, float* out, int F, int doElu) {
    size_t i = (size_t)blockIdx.x * blockDim.x + threadIdx.x;
    if (i >= (size_t)Nn * F) return;
    int n = (int)(i / F), d2 = (int)(i % F);
    const float* p = acc + (size_t)n * NH * F + d2;
    float v = (p[0] + p[F] + p[2 * F]) * (1.f / NH);
    if (doElu) v = eluf(v);
    out[i] = v;
}

// ---------------- MLP head ----------------
__global__ void k_mlp(const float* __restrict__ z, const float* __restrict__ w1,
                      const float* __restrict__ b1, const float* __restrict__ w2,
                      const float* __restrict__ b2, const int* __restrict__ flag,
                      float* yp) {
    int n = blockIdx.x;
    int t = threadIdx.x;
    __shared__ float zs[OUTF];
    __shared__ float hid[MHc];
    if (t < OUTF) zs[t] = z[(size_t)n * OUTF + t];
    __syncthreads();
    if (*flag == 0) {
        if (t < NLABc) yp[(size_t)n * NLABc + t] = 0.f;
        return;
    }
    float a = b1[t];
    #pragma unroll
    for (int k = 0; k < OUTF; k++) a += zs[k] * w1[k * MHc + t];
    hid[t] = fmaxf(a, 0.f);
    __syncthreads();
    if (t < NLABc) {
        float o = b2[t];
        #pragma unroll
        for (int k2 = 0; k2 < MHc; k2++) o += hid[k2] * w2[k2 * NLABc + t];
        yp[(size_t)n * NLABc + t] = o;
    }
}

// ---------------- fc2 (K=30, memory-bound) ----------------
__global__ void k_fc2(const float* __restrict__ z, const float* __restrict__ W,
                      const float* __restrict__ b, float* out) {
    size_t i = (size_t)blockIdx.x * blockDim.x + threadIdx.x;
    if (i >= (size_t)Nn * INF_) return;
    int n = (int)(i / INF_), j = (int)(i % INF_);
    float acc = b[j];
    const float* zr = z + (size_t)n * OUTF;
    #pragma unroll
    for (int k = 0; k < OUTF; k++) acc += zr[k] * W[(size_t)k * INF_ + j];
    out[i] = acc;
}

// ---------------- DSBN ----------------
__global__ void k_cnt(const int* __restrict__ y) {
    int n = blockIdx.x * blockDim.x + threadIdx.x;
    if (n < Nn) atomicAdd(&g_cnt[y[n]], 1.f);
}

__global__ void k_dsbn_sum(const float* __restrict__ X, const int* __restrict__ y) {
    int j = blockIdx.x * blockDim.x + threadIdx.x;
    if (j >= INF_) return;
    int chunk = (Nn + gridDim.y - 1) / gridDim.y;
    int n0 = blockIdx.y * chunk;
    int n1 = min(n0 + chunk, Nn);
    float a[NDOMc], b[NDOMc];
    #pragma unroll
    for (int k = 0; k < NDOMc; k++) { a[k] = 0.f; b[k] = 0.f; }
    for (int n = n0; n < n1; n++) {
        int d = y[n];
        float v = X[(size_t)n * INF_ + j];
        #pragma unroll
        for (int k = 0; k < NDOMc; k++) {
            float m = (d == k) ? 1.f : 0.f;
            a[k] += m * v;
            b[k] += m * v * v;
        }
    }
    #pragma unroll
    for (int k = 0; k < NDOMc; k++) {
        atomicAdd(&g_dsum[k * INF_ + j], a[k]);
        atomicAdd(&g_dsum2[k * INF_ + j], b[k]);
    }
}

// ======================================================================
extern "C" void kernel_launch(void* const* d_in, const int* in_sizes, int n_in,
                              void* d_out, int out_size) {
    const float* features = (const float*)d_in[0];
    const int*   ei       = (const int*)d_in[1];
    const int*   y        = (const int*)d_in[2];
    const int*   flag     = (const int*)d_in[3];
    const float* fc1_w    = (const float*)d_in[4];
    const float* fc1_b    = (const float*)d_in[5];
    const float* bn_g     = (const float*)d_in[6];
    const float* bn_b     = (const float*)d_in[7];
    const float* W1       = (const float*)d_in[8];
    const float* a1_src   = (const float*)d_in[9];
    const float* a1_dst   = (const float*)d_in[10];
    const float* W2       = (const float*)d_in[11];
    const float* a2_src   = (const float*)d_in[12];
    const float* a2_dst   = (const float*)d_in[13];
    const float* mlp_w1   = (const float*)d_in[14];
    const float* mlp_b1   = (const float*)d_in[15];
    const float* mlp_w2   = (const float*)d_in[16];
    const float* mlp_b2   = (const float*)d_in[17];
    const float* fc2_w    = (const float*)d_in[18];
    const float* fc2_b    = (const float*)d_in[19];
    const float* dsbn_g   = (const float*)d_in[20];
    const float* dsbn_b   = (const float*)d_in[21];
    const float* fc3_w    = (const float*)d_in[22];
    const float* fc3_b    = (const float*)d_in[23];

    float* out    = (float*)d_out;
    float* z_out  = out;
    float* h3_out = out + (size_t)Nn * OUTF;
    float* yp_out = h3_out + (size_t)Nn * INF_;
    const int* srcp = ei;
    const int* dstp = ei + Ee;

    void* p;
    cudaGetSymbolAddress(&p, g_x);     float* px    = (float*)p;
    cudaGetSymbolAddress(&p, g_H);     float* pH    = (float*)p;
    cudaGetSymbolAddress(&p, g_acc1);  float* pacc1 = (float*)p;
    cudaGetSymbolAddress(&p, g_h1);    float* ph1   = (float*)p;
    cudaGetSymbolAddress(&p, g_H2);    float* pH2   = (float*)p;
    cudaGetSymbolAddress(&p, g_acc2);  float* pacc2 = (float*)p;
    cudaGetSymbolAddress(&p, g_als1);  float* pals1 = (float*)p;
    cudaGetSymbolAddress(&p, g_ald1);  float* pald1 = (float*)p;
    cudaGetSymbolAddress(&p, g_als2);  float* pals2 = (float*)p;
    cudaGetSymbolAddress(&p, g_ald2);  float* pald2 = (float*)p;
    cudaGetSymbolAddress(&p, g_e1);    float* pe1   = (float*)p;
    cudaGetSymbolAddress(&p, g_e2);    float* pe2   = (float*)p;
    cudaGetSymbolAddress(&p, g_mkey1); unsigned* pmk1 = (unsigned*)p;
    cudaGetSymbolAddress(&p, g_mkey2); unsigned* pmk2 = (unsigned*)p;
    cudaGetSymbolAddress(&p, g_den1);  float* pden1 = (float*)p;
    cudaGetSymbolAddress(&p, g_den2);  float* pden2 = (float*)p;
    cudaGetSymbolAddress(&p, g_Ahi);   __nv_bfloat16* pAhi = (__nv_bfloat16*)p;
    cudaGetSymbolAddress(&p, g_Alo);   __nv_bfloat16* pAlo = (__nv_bfloat16*)p;
    cudaGetSymbolAddress(&p, g_Whi);   __nv_bfloat16* pWhi = (__nv_bfloat16*)p;
    cudaGetSymbolAddress(&p, g_Wlo);   __nv_bfloat16* pWlo = (__nv_bfloat16*)p;

    static int smem_set = 0;
    if (!smem_set) {
        cudaFuncSetAttribute(gemm_mma3, cudaFuncAttributeMaxDynamicSharedMemorySize, GSMEM);
        smem_set = 1;
    }

    const int nMt = (Nn + 127) / 128;
    const size_t splitGrid4 = ((size_t)Nn * (KPAD / 4) + 255) / 256;

    // 0) zero scratch
    {
        size_t tot = (size_t)Nn * NH * HIDF;
        k_zero<<<(unsigned)((tot + 255) / 256), 256>>>();
    }

    // 1) fc1
    {
        dim3 tg((KPAD + 31) / 32, (INF_ + 31) / 32);
        k_splitWT<<<tg, dim3(32, 32)>>>(fc1_w, pWhi, pWlo, INF_, INF_);
        k_splitA4<<<(unsigned)splitGrid4, 256>>>(features, pAhi, pAlo, Nn, INF_);
        int nNt = (INF_ + 127) / 128;
        gemm_mma3<<<nMt * nNt, 256, GSMEM>>>(pAhi, pAlo, pWhi, pWlo, fc1_b, px, Nn, INF_, nNt);
    }

    // 2) batchnorm stats + fused apply/ELU/split (writes GAT1 GEMM input directly)
    {
        dim3 grid((INF_ + 255) / 256, 128);
        k_colsum<<<grid, 256>>>(px);
        k_bn_elu_split<<<(unsigned)splitGrid4, 256>>>(px, bn_g, bn_b, pAhi, pAlo);
    }

    // 3) GAT layer 1
    {
        dim3 tg((KPAD + 31) / 32, (NH * HIDF + 31) / 32);
        k_splitWT<<<tg, dim3(32, 32)>>>(W1, pWhi, pWlo, INF_, NH * HIDF);
        int nNt = (NH * HIDF + 127) / 128;
        gemm_mma3<<<nMt * nNt, 256, GSMEM>>>(pAhi, pAlo, pWhi, pWlo, nullptr, pH, Nn, NH * HIDF, nNt);

        int warps = Nn * NH;
        k_attn_logits<<<(warps * 32 + 127) / 128, 128>>>(pH, a1_src, a1_dst, pals1, pald1, HIDF);

        int et = Ee * NH;
        k_edge_max<<<(et + 255) / 256, 256>>>(srcp, dstp, pals1, pald1, pe1, pmk1);
        k_edge_exp<<<(et + 255) / 256, 256>>>(dstp, pe1, pmk1, pden1);
        k_scatter4<<<Ee, 256>>>(srcp, dstp, pH, pe1, pden1, pacc1, HIDF);

        size_t tot = (size_t)Nn * HIDF;
        k_mean<<<(unsigned)((tot + 255) / 256), 256>>>(pacc1, ph1, HIDF, 1);
    }

    // 4) GAT layer 2 -> z
    {
        dim3 grid((NH * OUTF + BN - 1) / BN, (Nn + BM - 1) / BM);
        sgemm_k<<<grid, 256>>>(ph1, W2, nullptr, pH2, Nn, NH * OUTF, HIDF);

        int warps = Nn * NH;
        k_attn_logits<<<(warps * 32 + 127) / 128, 128>>>(pH2, a2_src, a2_dst, pals2, pald2, OUTF);

        int et = Ee * NH;
        k_edge_max<<<(et + 255) / 256, 256>>>(srcp, dstp, pals2, pald2, pe2, pmk2);
        k_edge_exp<<<(et + 255) / 256, 256>>>(dstp, pe2, pmk2, pden2);
        k_scatter<<<Ee, 128>>>(srcp, dstp, pH2, pe2, pden2, pacc2, OUTF);

        size_t tot = (size_t)Nn * OUTF;
        k_mean<<<(unsigned)((tot + 255) / 256), 256>>>(pacc2, z_out, OUTF, 0);
    }

    // 5) MLP head
    k_mlp<<<Nn, MHc>>>(z_out, mlp_w1, mlp_b1, mlp_w2, mlp_b2, flag, yp_out);

    // 6) fc2 -> DSBN stats -> fused apply/ELU/split (writes fc3 GEMM input directly)
    {
        size_t tot = (size_t)Nn * INF_;
        k_fc2<<<(unsigned)((tot + 255) / 256), 256>>>(z_out, fc2_w, fc2_b, px);
        k_cnt<<<(Nn + 255) / 256, 256>>>(y);
        dim3 grid((INF_ + 255) / 256, 128);
        k_dsbn_sum<<<grid, 256>>>(px, y);
        k_dsbn_elu_split<<<(unsigned)splitGrid4, 256>>>(px, y, dsbn_g, dsbn_b, pAhi, pAlo);
    }

    // 7) fc3 -> h3
    {
        dim3 tg((KPAD + 31) / 32, (INF_ + 31) / 32);
        k_splitWT<<<tg, dim3(32, 32)>>>(fc3_w, pWhi, pWlo, INF_, INF_);
        int nNt = (INF_ + 127) / 128;
        gemm_mma3<<<nMt * nNt, 256, GSMEM>>>(pAhi, pAlo, pWhi, pWlo, fc3_b, h3_out, Nn, INF_, nNt);
    }
}

// round 10
// speedup vs baseline: 1.7630x; 1.5983x over previous
#include <cuda_runtime.h>
#include <cuda_bf16.h>
#include <cuda_fp16.h>
#include <math.h>
#include <stdint.h>

#define Nn    20000
#define Ee    120000
#define INF_  3000
#define HIDF  512
#define OUTF  30
#define NH    3
#define NDOMc 4
#define MHc   64
#define NLABc 20
#define EPSBN 1e-5f
#define KPAD  3008                 // 3000 padded to multiple of 32

// ---------------- scratch (static device memory; no allocations) ----------------
__device__ float    g_x[(size_t)Nn * INF_];
__device__ float    g_H[(size_t)Nn * NH * HIDF];
__device__ float    g_acc1[(size_t)Nn * NH * HIDF];
__device__ float    g_h1[(size_t)Nn * HIDF];
__device__ float    g_H2[(size_t)Nn * NH * OUTF];
__device__ float    g_acc2[(size_t)Nn * NH * OUTF];
__device__ float    g_als1[Nn * NH], g_ald1[Nn * NH];
__device__ float    g_als2[Nn * NH], g_ald2[Nn * NH];
__device__ float    g_e1[(size_t)Ee * NH];
__device__ float    g_e2[(size_t)Ee * NH];
__device__ unsigned g_mkey1[Nn * NH], g_mkey2[Nn * NH];
__device__ float    g_den1[Nn * NH], g_den2[Nn * NH];
__device__ float    g_bnsum[INF_], g_bnsum2[INF_];
__device__ float    g_dsum[NDOMc * INF_], g_dsum2[NDOMc * INF_];
__device__ float    g_cnt[NDOMc];
__device__ __align__(256) __half g_Ahi[(size_t)Nn * KPAD];
__device__ __align__(256) __half g_Alo[(size_t)Nn * KPAD];
__device__ __align__(256) __half g_Wq[(size_t)INF_ * KPAD];   // transposed weights [N, KPAD]

// ---------------- helpers ----------------
__device__ __forceinline__ unsigned f2o(float f) {
    unsigned u = __float_as_uint(f);
    return (u & 0x80000000u) ? ~u : (u | 0x80000000u);
}
__device__ __forceinline__ float o2f(unsigned k) {
    return (k & 0x80000000u) ? __uint_as_float(k ^ 0x80000000u) : __uint_as_float(~k);
}
__device__ __forceinline__ float eluf(float v) { return v > 0.f ? v : (expf(v) - 1.f); }

__device__ __forceinline__ uint32_t smem_u32(const void* p) {
    uint32_t a;
    asm("{ .reg .u64 t; cvta.to.shared.u64 t, %1; cvt.u32.u64 %0, t; }" : "=r"(a) : "l"(p));
    return a;
}

__device__ __forceinline__ void cp16(uint32_t dst, const void* src, int ok) {
    asm volatile("cp.async.cg.shared.global [%0], [%1], 16, %2;"
                 :: "r"(dst), "l"(src), "r"(ok ? 16 : 0) : "memory");
}
#define CP_COMMIT() asm volatile("cp.async.commit_group;" ::: "memory")
#define CP_WAIT1()  asm volatile("cp.async.wait_group 1;" ::: "memory")

__device__ __forceinline__ void mma16816(float* c, const uint32_t* a, const uint32_t* b) {
    asm volatile(
        "mma.sync.aligned.m16n8k16.row.col.f32.f16.f16.f32 "
        "{%0,%1,%2,%3},{%4,%5,%6,%7},{%8,%9},{%0,%1,%2,%3};"
        : "+f"(c[0]), "+f"(c[1]), "+f"(c[2]), "+f"(c[3])
        : "r"(a[0]), "r"(a[1]), "r"(a[2]), "r"(a[3]), "r"(b[0]), "r"(b[1]));
}
__device__ __forceinline__ void ldsm_x4(uint32_t* r, uint32_t addr) {
    asm volatile("ldmatrix.sync.aligned.m8n8.x4.shared.b16 {%0,%1,%2,%3}, [%4];"
                 : "=r"(r[0]), "=r"(r[1]), "=r"(r[2]), "=r"(r[3]) : "r"(addr));
}

// ---------------- split helpers (fp16 hi/lo) ----------------
__device__ __forceinline__ void split_store4(__half* hi, __half* lo, size_t o,
                                             float v0, float v1, float v2, float v3) {
    __half h0 = __float2half_rn(v0), h1 = __float2half_rn(v1);
    __half h2 = __float2half_rn(v2), h3 = __float2half_rn(v3);
    __half2 hp0 = __halves2half2(h0, h1), hp1 = __halves2half2(h2, h3);
    __half2 lp0 = __halves2half2(__float2half_rn(v0 - __half2float(h0)),
                                 __float2half_rn(v1 - __half2float(h1)));
    __half2 lp1 = __halves2half2(__float2half_rn(v2 - __half2float(h2)),
                                 __float2half_rn(v3 - __half2float(h3)));
    uint2 hv, lv;
    hv.x = *(uint32_t*)&hp0; hv.y = *(uint32_t*)&hp1;
    lv.x = *(uint32_t*)&lp0; lv.y = *(uint32_t*)&lp1;
    *reinterpret_cast<uint2*>(hi + o) = hv;
    *reinterpret_cast<uint2*>(lo + o) = lv;
}

__global__ void k_splitA4(const float* __restrict__ X, __half* __restrict__ hi,
                          __half* __restrict__ lo, int M, int K) {
    size_t i4 = (size_t)blockIdx.x * blockDim.x + threadIdx.x;
    const int kq = KPAD / 4;
    if (i4 >= (size_t)M * kq) return;
    int m = (int)(i4 / kq), k4 = (int)(i4 % kq) * 4;
    const float* row = X + (size_t)m * K;
    float v0, v1, v2, v3;
    if (k4 + 3 < K) {
        float4 f = *reinterpret_cast<const float4*>(row + k4);
        v0 = f.x; v1 = f.y; v2 = f.z; v3 = f.w;
    } else {
        v0 = (k4 + 0 < K) ? row[k4 + 0] : 0.f;
        v1 = (k4 + 1 < K) ? row[k4 + 1] : 0.f;
        v2 = (k4 + 2 < K) ? row[k4 + 2] : 0.f;
        v3 = (k4 + 3 < K) ? row[k4 + 3] : 0.f;
    }
    split_store4(hi, lo, (size_t)m * KPAD + k4, v0, v1, v2, v3);
}

// Fused: BN apply + ELU + fp16 split
__global__ void k_bn_elu_split(const float* __restrict__ X,
                               const float* __restrict__ g, const float* __restrict__ b,
                               __half* __restrict__ hi, __half* __restrict__ lo) {
    size_t i4 = (size_t)blockIdx.x * blockDim.x + threadIdx.x;
    const int kq = KPAD / 4;
    if (i4 >= (size_t)Nn * kq) return;
    int m = (int)(i4 / kq), k4 = (int)(i4 % kq) * 4;
    float v[4];
    if (k4 + 3 < INF_) {
        float4 f = *reinterpret_cast<const float4*>(X + (size_t)m * INF_ + k4);
        v[0] = f.x; v[1] = f.y; v[2] = f.z; v[3] = f.w;
#pragma unroll
        for (int q = 0; q < 4; q++) {
            int j = k4 + q;
            float mu  = g_bnsum[j] * (1.f / Nn);
            float var = fmaxf(g_bnsum2[j] * (1.f / Nn) - mu * mu, 0.f);
            v[q] = eluf((v[q] - mu) * rsqrtf(var + EPSBN) * g[j] + b[j]);
        }
    } else {
#pragma unroll
        for (int q = 0; q < 4; q++) {
            int j = k4 + q;
            if (j < INF_) {
                float x = X[(size_t)m * INF_ + j];
                float mu  = g_bnsum[j] * (1.f / Nn);
                float var = fmaxf(g_bnsum2[j] * (1.f / Nn) - mu * mu, 0.f);
                v[q] = eluf((x - mu) * rsqrtf(var + EPSBN) * g[j] + b[j]);
            } else v[q] = 0.f;
        }
    }
    split_store4(hi, lo, (size_t)m * KPAD + k4, v[0], v[1], v[2], v[3]);
}

// Fused: DSBN apply + ELU + fp16 split
__global__ void k_dsbn_elu_split(const float* __restrict__ X, const int* __restrict__ y,
                                 const float* __restrict__ gmm, const float* __restrict__ bta,
                                 __half* __restrict__ hi, __half* __restrict__ lo) {
    size_t i4 = (size_t)blockIdx.x * blockDim.x + threadIdx.x;
    const int kq = KPAD / 4;
    if (i4 >= (size_t)Nn * kq) return;
    int m = (int)(i4 / kq), k4 = (int)(i4 % kq) * 4;
    int d = y[m];
    float c = g_cnt[d];
    bool norm = (c > 1.f);
    float inv = norm ? (1.f / c) : 0.f;
    float v[4];
#pragma unroll
    for (int q = 0; q < 4; q++) {
        int j = k4 + q;
        if (j < INF_) {
            float x = X[(size_t)m * INF_ + j];
            float o = x;
            if (norm) {
                float mu  = g_dsum[d * INF_ + j] * inv;
                float var = fmaxf(g_dsum2[d * INF_ + j] * inv - mu * mu, 0.f);
                o = (x - mu) * rsqrtf(var + EPSBN) * gmm[d * INF_ + j] + bta[d * INF_ + j];
            }
            v[q] = eluf(o);
        } else v[q] = 0.f;
    }
    split_store4(hi, lo, (size_t)m * KPAD + k4, v[0], v[1], v[2], v[3]);
}

// W[K, N] f32 -> WT fp16 [N, KPAD] (zero pad beyond K)
__global__ void k_splitWT(const float* __restrict__ W, __half* __restrict__ hi,
                          int K, int Nmat) {
    __shared__ float t[32][33];
    int kb = blockIdx.x * 32, nb = blockIdx.y * 32;
    int rk = kb + threadIdx.y, rn = nb + threadIdx.x;
    t[threadIdx.y][threadIdx.x] = (rk < K && rn < Nmat) ? W[(size_t)rk * Nmat + rn] : 0.f;
    __syncthreads();
    int wn = nb + threadIdx.y, wk = kb + threadIdx.x;
    if (wn < Nmat && wk < KPAD)
        hi[(size_t)wn * KPAD + wk] = __float2half_rn(t[threadIdx.x][threadIdx.y]);
}

// ------ mma.sync fp16 2-term GEMM: 256 thr, ldmatrix, 2 CTAs/SM ------
#define ROWB      80
#define TILE_PAD  (128 * ROWB)           // 10240 B
#define STAGE_B   (3 * TILE_PAD)         // 30720 B  (Ahi, Alo, B)
#define GSMEM     (2 * STAGE_B)          // 61440 B

__device__ __forceinline__ void ld_stage(
    uint32_t sb,
    const __half* __restrict__ Ahi, const __half* __restrict__ Alo,
    const __half* __restrict__ Bq,
    int m0, int n0, int M, int Nmat, int kb, int tid)
{
    int row = tid >> 1;
    int cb = (tid & 1) * 32;              // byte offset within the 64B row data
    int ce = cb >> 1;                     // element offset (halves)

    int gA = m0 + row;
    int okA = gA < M;
    const __half* a  = Ahi + (size_t)(okA ? gA : 0) * KPAD + kb + ce;
    const __half* al = Alo + (size_t)(okA ? gA : 0) * KPAD + kb + ce;
    uint32_t soA = sb + (uint32_t)row * ROWB + (uint32_t)cb;
    cp16(soA,      a,      okA);
    cp16(soA + 16, a + 8,  okA);
    cp16(soA + TILE_PAD,      al,     okA);
    cp16(soA + TILE_PAD + 16, al + 8, okA);

    int gB = n0 + row;
    int okB = gB < Nmat;
    const __half* b = Bq + (size_t)(okB ? gB : 0) * KPAD + kb + ce;
    uint32_t soB = sb + 2 * TILE_PAD + (uint32_t)row * ROWB + (uint32_t)cb;
    cp16(soB,      b,     okB);
    cp16(soB + 16, b + 8, okB);
}

__global__ void __launch_bounds__(256, 2) gemm_mma3(
    const __half* __restrict__ Ahi, const __half* __restrict__ Alo,
    const __half* __restrict__ Bq,
    const float* __restrict__ bias, float* __restrict__ C,
    int M, int Nmat, int nNt)
{
    extern __shared__ char smem[];
    uint32_t sbase = smem_u32(smem);
    int tid = threadIdx.x, lane = tid & 31, wid = tid >> 5;
    int wm = wid >> 2, wn = wid & 3;          // warp grid 2x4; warp tile 64x32
    int gID = lane >> 2, tg = lane & 3;
    int bid = blockIdx.x;
    int nt = bid % nNt, mt = bid / nNt;
    int m0 = mt * 128, n0 = nt * 128;
    const int nK = KPAD / 32;

    float acc[4][4][4];
#pragma unroll
    for (int i = 0; i < 4; i++)
#pragma unroll
        for (int j = 0; j < 4; j++)
#pragma unroll
            for (int q = 0; q < 4; q++) acc[i][j][q] = 0.f;

    ld_stage(sbase, Ahi, Alo, Bq, m0, n0, M, Nmat, 0, tid);
    CP_COMMIT();

    uint32_t aOff[4], bOff[2];
#pragma unroll
    for (int mi = 0; mi < 4; mi++)
        aOff[mi] = (uint32_t)(wm * 64 + mi * 16 + (lane & 15)) * ROWB + (uint32_t)(lane >> 4) * 16;
#pragma unroll
    for (int pp = 0; pp < 2; pp++)
        bOff[pp] = (uint32_t)(wn * 32 + pp * 16 + ((lane >> 4) << 3) + (lane & 7)) * ROWB
                 + (uint32_t)(((lane >> 3) & 1) << 4);

    for (int kt = 0; kt < nK; kt++) {
        if (kt + 1 < nK)
            ld_stage(sbase + (uint32_t)((kt + 1) & 1) * STAGE_B,
                     Ahi, Alo, Bq, m0, n0, M, Nmat, (kt + 1) * 32, tid);
        CP_COMMIT();
        CP_WAIT1();
        __syncthreads();

        uint32_t sb = sbase + (uint32_t)(kt & 1) * STAGE_B;
#pragma unroll
        for (int ks = 0; ks < 2; ks++) {
            uint32_t kb2 = (uint32_t)ks * 32;
            uint32_t bh[2][4];
#pragma unroll
            for (int pp = 0; pp < 2; pp++)
                ldsm_x4(bh[pp], sb + 2 * TILE_PAD + bOff[pp] + kb2);
#pragma unroll
            for (int mi = 0; mi < 4; mi++) {
                uint32_t ah[4], al[4];
                ldsm_x4(ah, sb + aOff[mi] + kb2);
                ldsm_x4(al, sb + TILE_PAD + aOff[mi] + kb2);
#pragma unroll
                for (int ni = 0; ni < 4; ni++) {
                    uint32_t* Bh = &bh[ni >> 1][(ni & 1) * 2];
                    mma16816(acc[mi][ni], ah, Bh);
                    mma16816(acc[mi][ni], al, Bh);
                }
            }
        }
        __syncthreads();
    }

#pragma unroll
    for (int mi = 0; mi < 4; mi++) {
        int r0 = m0 + wm * 64 + mi * 16 + gID;
        int r1 = r0 + 8;
#pragma unroll
        for (int ni = 0; ni < 4; ni++) {
            int cbase = n0 + wn * 32 + ni * 8 + tg * 2;
            if (cbase >= Nmat) continue;
            bool two = (cbase + 1 < Nmat);
            float bx = bias ? bias[cbase] : 0.f;
            float by = (bias && two) ? bias[cbase + 1] : 0.f;
            if (r0 < M) {
                float* p = C + (size_t)r0 * Nmat + cbase;
                if (two) { p[0] = acc[mi][ni][0] + bx; p[1] = acc[mi][ni][1] + by; }
                else p[0] = acc[mi][ni][0] + bx;
            }
            if (r1 < M) {
                float* p = C + (size_t)r1 * Nmat + cbase;
                if (two) { p[0] = acc[mi][ni][2] + bx; p[1] = acc[mi][ni][3] + by; }
                else p[0] = acc[mi][ni][2] + bx;
            }
        }
    }
}

// ---------------- zero scratch ----------------
__global__ void k_zero() {
    size_t i = (size_t)blockIdx.x * blockDim.x + threadIdx.x;
    if (i < (size_t)Nn * NH * HIDF) g_acc1[i] = 0.f;
    if (i < (size_t)Nn * NH * OUTF) g_acc2[i] = 0.f;
    if (i < Nn * NH) {
        g_mkey1[i] = 0u; g_den1[i] = 0.f;
        g_mkey2[i] = 0u; g_den2[i] = 0.f;
    }
    if (i < INF_) { g_bnsum[i] = 0.f; g_bnsum2[i] = 0.f; }
    if (i < NDOMc * INF_) { g_dsum[i] = 0.f; g_dsum2[i] = 0.f; }
    if (i < NDOMc) g_cnt[i] = 0.f;
}

// ---------------- tiled SGEMM (GAT2 small GEMM) ----------------
#define BM 128
#define BN 128
#define BK 8
#define TM 8
#define TN 8
__global__ __launch_bounds__(256) void sgemm_k(
    const float* __restrict__ A, const float* __restrict__ B,
    const float* __restrict__ bias, float* __restrict__ C,
    int M, int Nc, int K)
{
    __shared__ float As[BK][BM];
    __shared__ float Bs[BK][BN];
    int tid = threadIdx.x;
    int m0 = blockIdx.y * BM;
    int n0 = blockIdx.x * BN;
    int tx = tid & 15, ty = tid >> 4;

    float acc[TM][TN];
    #pragma unroll
    for (int i = 0; i < TM; i++)
        #pragma unroll
        for (int j = 0; j < TN; j++) acc[i][j] = 0.f;

    int aRow = tid >> 1;
    int aCol = (tid & 1) * 4;
    int bRow = tid >> 5;
    int bCol = (tid & 31) * 4;

    int nK = K / BK;
    for (int kt = 0; kt < nK; kt++) {
        int kb = kt * BK;
        float4 av = make_float4(0.f, 0.f, 0.f, 0.f);
        if (m0 + aRow < M)
            av = *reinterpret_cast<const float4*>(A + (size_t)(m0 + aRow) * K + kb + aCol);
        As[aCol + 0][aRow] = av.x; As[aCol + 1][aRow] = av.y;
        As[aCol + 2][aRow] = av.z; As[aCol + 3][aRow] = av.w;

        const float* Bp = B + (size_t)(kb + bRow) * Nc + n0 + bCol;
        float4 bv;
        if (n0 + bCol + 3 < Nc && ((((size_t)Bp) & 15) == 0)) {
            bv = *reinterpret_cast<const float4*>(Bp);
        } else {
            bv.x = (n0 + bCol + 0 < Nc) ? Bp[0] : 0.f;
            bv.y = (n0 + bCol + 1 < Nc) ? Bp[1] : 0.f;
            bv.z = (n0 + bCol + 2 < Nc) ? Bp[2] : 0.f;
            bv.w = (n0 + bCol + 3 < Nc) ? Bp[3] : 0.f;
        }
        Bs[bRow][bCol + 0] = bv.x; Bs[bRow][bCol + 1] = bv.y;
        Bs[bRow][bCol + 2] = bv.z; Bs[bRow][bCol + 3] = bv.w;
        __syncthreads();

        #pragma unroll
        for (int k = 0; k < BK; k++) {
            float ar[TM], br[TN];
            #pragma unroll
            for (int i = 0; i < TM; i++) ar[i] = As[k][ty * TM + i];
            #pragma unroll
            for (int j = 0; j < TN; j++) br[j] = Bs[k][tx * TN + j];
            #pragma unroll
            for (int i = 0; i < TM; i++)
                #pragma unroll
                for (int j = 0; j < TN; j++) acc[i][j] += ar[i] * br[j];
        }
        __syncthreads();
    }

    #pragma unroll
    for (int i = 0; i < TM; i++) {
        int m = m0 + ty * TM + i;
        if (m >= M) continue;
        #pragma unroll
        for (int j = 0; j < TN; j++) {
            int n = n0 + tx * TN + j;
            if (n >= Nc) continue;
            float v = acc[i][j];
            if (bias) v += bias[n];
            C[(size_t)m * Nc + n] = v;
        }
    }
}

// ---------------- batch-norm column sums ----------------
__global__ void k_colsum(const float* __restrict__ X) {
    int j = blockIdx.x * blockDim.x + threadIdx.x;
    if (j >= INF_) return;
    int chunk = (Nn + gridDim.y - 1) / gridDim.y;
    int n0 = blockIdx.y * chunk;
    int n1 = min(n0 + chunk, Nn);
    float a = 0.f, b = 0.f;
    for (int n = n0; n < n1; n++) {
        float v = X[(size_t)n * INF_ + j];
        a += v; b += v * v;
    }
    atomicAdd(&g_bnsum[j], a);
    atomicAdd(&g_bnsum2[j], b);
}

// ---------------- attention logits: warp per (n, h) ----------------
__global__ void k_attn_logits(const float* __restrict__ Hh, const float* __restrict__ asrc,
                              const float* __restrict__ adst, float* als, float* ald, int F) {
    int w = (int)(((size_t)blockIdx.x * blockDim.x + threadIdx.x) >> 5);
    int lane = threadIdx.x & 31;
    if (w >= Nn * NH) return;
    int h = w % NH;
    const float* hp = Hh + (size_t)w * F;
    float s = 0.f, d = 0.f;
    for (int t = lane; t < F; t += 32) {
        float hv = hp[t];
        s += hv * asrc[h * F + t];
        d += hv * adst[h * F + t];
    }
    #pragma unroll
    for (int o = 16; o; o >>= 1) {
        s += __shfl_down_sync(0xffffffffu, s, o);
        d += __shfl_down_sync(0xffffffffu, d, o);
    }
    if (lane == 0) { als[w] = s; ald[w] = d; }
}

// ---------------- edge softmax ----------------
__global__ void k_edge_max(const int* __restrict__ src, const int* __restrict__ dst,
                           const float* __restrict__ als, const float* __restrict__ ald,
                           float* e, unsigned* mkey) {
    int i = blockIdx.x * blockDim.x + threadIdx.x;
    if (i >= Ee * NH) return;
    int ed = i / NH, h = i % NH;
    float v = als[src[ed] * NH + h] + ald[dst[ed] * NH + h];
    v = v > 0.f ? v : 0.2f * v;
    e[i] = v;
    atomicMax(&mkey[dst[ed] * NH + h], f2o(v));
}

__global__ void k_edge_exp(const int* __restrict__ dst, float* e,
                           const unsigned* __restrict__ mkey, float* den) {
    int i = blockIdx.x * blockDim.x + threadIdx.x;
    if (i >= Ee * NH) return;
    int ed = i / NH, h = i % NH;
    float m = o2f(mkey[dst[ed] * NH + h]);
    float ex = expf(e[i] - m);
    e[i] = ex;
    atomicAdd(&den[dst[ed] * NH + h], ex);
}

// ---------------- weighted message scatter ----------------
__global__ void k_scatter4(const int* __restrict__ src, const int* __restrict__ dst,
                           const float* __restrict__ Hh, const float* __restrict__ e,
                           const float* __restrict__ den, float* out, int F) {
    int ed = blockIdx.x;
    int s = src[ed], d = dst[ed];
    __shared__ float alpha[NH];
    if (threadIdx.x < NH)
        alpha[threadIdx.x] = e[ed * NH + threadIdx.x] / (den[d * NH + threadIdx.x] + 1e-16f);
    __syncthreads();
    int tot4 = NH * F / 4;
    int fq = F / 4;
    const float4* Hs = reinterpret_cast<const float4*>(Hh + (size_t)s * NH * F);
    float* od = out + (size_t)d * NH * F;
    for (int i4 = threadIdx.x; i4 < tot4; i4 += blockDim.x) {
        int h = i4 / fq;
        float a = alpha[h];
        float4 v = Hs[i4];
        int base = i4 * 4;
        atomicAdd(&od[base + 0], v.x * a);
        atomicAdd(&od[base + 1], v.y * a);
        atomicAdd(&od[base + 2], v.z * a);
        atomicAdd(&od[base + 3], v.w * a);
    }
}

__global__ void k_scatter(const int* __restrict__ src, const int* __restrict__ dst,
                          const float* __restrict__ Hh, const float* __restrict__ e,
                          const float* __restrict__ den, float* out, int F) {
    int ed = blockIdx.x;
    int s = src[ed], d = dst[ed];
    __shared__ float alpha[NH];
    if (threadIdx.x < NH)
        alpha[threadIdx.x] = e[ed * NH + threadIdx.x] / (den[d * NH + threadIdx.x] + 1e-16f);
    __syncthreads();
    int tot = NH * F;
    for (int idx = threadIdx.x; idx < tot; idx += blockDim.x) {
        int h = idx / F;
        atomicAdd(&out[(size_t)d * tot + idx], Hh[(size_t)s * tot + idx] * alpha[h]);
    }
}

// ---------------- head mean (+ optional ELU) ----------------
__global__ void k_mean(const float* __restrict__ acc, float* out, int F, int doElu) {
    size_t i = (size_t)blockIdx.x * blockDim.x + threadIdx.x;
    if (i >= (size_t)Nn * F) return;
    int n = (int)(i / F), d2 = (int)(i % F);
    const float* p = acc + (size_t)n * NH * F + d2;
    float v = (p[0] + p[F] + p[2 * F]) * (1.f / NH);
    if (doElu) v = eluf(v);
    out[i] = v;
}

// ---------------- MLP head ----------------
__global__ void k_mlp(const float* __restrict__ z, const float* __restrict__ w1,
                      const float* __restrict__ b1, const float* __restrict__ w2,
                      const float* __restrict__ b2, const int* __restrict__ flag,
                      float* yp) {
    int n = blockIdx.x;
    int t = threadIdx.x;
    __shared__ float zs[OUTF];
    __shared__ float hid[MHc];
    if (t < OUTF) zs[t] = z[(size_t)n * OUTF + t];
    __syncthreads();
    if (*flag == 0) {
        if (t < NLABc) yp[(size_t)n * NLABc + t] = 0.f;
        return;
    }
    float a = b1[t];
    #pragma unroll
    for (int k = 0; k < OUTF; k++) a += zs[k] * w1[k * MHc + t];
    hid[t] = fmaxf(a, 0.f);
    __syncthreads();
    if (t < NLABc) {
        float o = b2[t];
        #pragma unroll
        for (int k2 = 0; k2 < MHc; k2++) o += hid[k2] * w2[k2 * NLABc + t];
        yp[(size_t)n * NLABc + t] = o;
    }
}

// ---------------- fc2 (K=30, memory-bound) ----------------
__global__ void k_fc2(const float* __restrict__ z, const float* __restrict__ W,
                      const float* __restrict__ b, float* out) {
    size_t i = (size_t)blockIdx.x * blockDim.x + threadIdx.x;
    if (i >= (size_t)Nn * INF_) return;
    int n = (int)(i / INF_), j = (int)(i % INF_);
    float acc = b[j];
    const float* zr = z + (size_t)n * OUTF;
    #pragma unroll
    for (int k = 0; k < OUTF; k++) acc += zr[k] * W[(size_t)k * INF_ + j];
    out[i] = acc;
}

// ---------------- DSBN ----------------
__global__ void k_cnt(const int* __restrict__ y) {
    int n = blockIdx.x * blockDim.x + threadIdx.x;
    if (n < Nn) atomicAdd(&g_cnt[y[n]], 1.f);
}

__global__ void k_dsbn_sum(const float* __restrict__ X, const int* __restrict__ y) {
    int j = blockIdx.x * blockDim.x + threadIdx.x;
    if (j >= INF_) return;
    int chunk = (Nn + gridDim.y - 1) / gridDim.y;
    int n0 = blockIdx.y * chunk;
    int n1 = min(n0 + chunk, Nn);
    float a[NDOMc], b[NDOMc];
    #pragma unroll
    for (int k = 0; k < NDOMc; k++) { a[k] = 0.f; b[k] = 0.f; }
    for (int n = n0; n < n1; n++) {
        int d = y[n];
        float v = X[(size_t)n * INF_ + j];
        #pragma unroll
        for (int k = 0; k < NDOMc; k++) {
            float m = (d == k) ? 1.f : 0.f;
            a[k] += m * v;
            b[k] += m * v * v;
        }
    }
    #pragma unroll
    for (int k = 0; k < NDOMc; k++) {
        atomicAdd(&g_dsum[k * INF_ + j], a[k]);
        atomicAdd(&g_dsum2[k * INF_ + j], b[k]);
    }
}

// ======================================================================
extern "C" void kernel_launch(void* const* d_in, const int* in_sizes, int n_in,
                              void* d_out, int out_size) {
    const float* features = (const float*)d_in[0];
    const int*   ei       = (const int*)d_in[1];
    const int*   y        = (const int*)d_in[2];
    const int*   flag     = (const int*)d_in[3];
    const float* fc1_w    = (const float*)d_in[4];
    const float* fc1_b    = (const float*)d_in[5];
    const float* bn_g     = (const float*)d_in[6];
    const float* bn_b     = (const float*)d_in[7];
    const float* W1       = (const float*)d_in[8];
    const float* a1_src   = (const float*)d_in[9];
    const float* a1_dst   = (const float*)d_in[10];
    const float* W2       = (const float*)d_in[11];
    const float* a2_src   = (const float*)d_in[12];
    const float* a2_dst   = (const float*)d_in[13];
    const float* mlp_w1   = (const float*)d_in[14];
    const float* mlp_b1   = (const float*)d_in[15];
    const float* mlp_w2   = (const float*)d_in[16];
    const float* mlp_b2   = (const float*)d_in[17];
    const float* fc2_w    = (const float*)d_in[18];
    const float* fc2_b    = (const float*)d_in[19];
    const float* dsbn_g   = (const float*)d_in[20];
    const float* dsbn_b   = (const float*)d_in[21];
    const float* fc3_w    = (const float*)d_in[22];
    const float* fc3_b    = (const float*)d_in[23];

    float* out    = (float*)d_out;
    float* z_out  = out;
    float* h3_out = out + (size_t)Nn * OUTF;
    float* yp_out = h3_out + (size_t)Nn * INF_;
    const int* srcp = ei;
    const int* dstp = ei + Ee;

    void* p;
    cudaGetSymbolAddress(&p, g_x);     float* px    = (float*)p;
    cudaGetSymbolAddress(&p, g_H);     float* pH    = (float*)p;
    cudaGetSymbolAddress(&p, g_acc1);  float* pacc1 = (float*)p;
    cudaGetSymbolAddress(&p, g_h1);    float* ph1   = (float*)p;
    cudaGetSymbolAddress(&p, g_H2);    float* pH2   = (float*)p;
    cudaGetSymbolAddress(&p, g_acc2);  float* pacc2 = (float*)p;
    cudaGetSymbolAddress(&p, g_als1);  float* pals1 = (float*)p;
    cudaGetSymbolAddress(&p, g_ald1);  float* pald1 = (float*)p;
    cudaGetSymbolAddress(&p, g_als2);  float* pals2 = (float*)p;
    cudaGetSymbolAddress(&p, g_ald2);  float* pald2 = (float*)p;
    cudaGetSymbolAddress(&p, g_e1);    float* pe1   = (float*)p;
    cudaGetSymbolAddress(&p, g_e2);    float* pe2   = (float*)p;
    cudaGetSymbolAddress(&p, g_mkey1); unsigned* pmk1 = (unsigned*)p;
    cudaGetSymbolAddress(&p, g_mkey2); unsigned* pmk2 = (unsigned*)p;
    cudaGetSymbolAddress(&p, g_den1);  float* pden1 = (float*)p;
    cudaGetSymbolAddress(&p, g_den2);  float* pden2 = (float*)p;
    cudaGetSymbolAddress(&p, g_Ahi);   __half* pAhi = (__half*)p;
    cudaGetSymbolAddress(&p, g_Alo);   __half* pAlo = (__half*)p;
    cudaGetSymbolAddress(&p, g_Wq);    __half* pWq  = (__half*)p;

    static int smem_set = 0;
    if (!smem_set) {
        cudaFuncSetAttribute(gemm_mma3, cudaFuncAttributeMaxDynamicSharedMemorySize, GSMEM);
        smem_set = 1;
    }

    const int nMt = (Nn + 127) / 128;
    const size_t splitGrid4 = ((size_t)Nn * (KPAD / 4) + 255) / 256;

    // 0) zero scratch
    {
        size_t tot = (size_t)Nn * NH * HIDF;
        k_zero<<<(unsigned)((tot + 255) / 256), 256>>>();
    }

    // 1) fc1
    {
        dim3 tg((KPAD + 31) / 32, (INF_ + 31) / 32);
        k_splitWT<<<tg, dim3(32, 32)>>>(fc1_w, pWq, INF_, INF_);
        k_splitA4<<<(unsigned)splitGrid4, 256>>>(features, pAhi, pAlo, Nn, INF_);
        int nNt = (INF_ + 127) / 128;
        gemm_mma3<<<nMt * nNt, 256, GSMEM>>>(pAhi, pAlo, pWq, fc1_b, px, Nn, INF_, nNt);
    }

    // 2) batchnorm stats + fused apply/ELU/split
    {
        dim3 grid((INF_ + 255) / 256, 128);
        k_colsum<<<grid, 256>>>(px);
        k_bn_elu_split<<<(unsigned)splitGrid4, 256>>>(px, bn_g, bn_b, pAhi, pAlo);
    }

    // 3) GAT layer 1
    {
        dim3 tg((KPAD + 31) / 32, (NH * HIDF + 31) / 32);
        k_splitWT<<<tg, dim3(32, 32)>>>(W1, pWq, INF_, NH * HIDF);
        int nNt = (NH * HIDF + 127) / 128;
        gemm_mma3<<<nMt * nNt, 256, GSMEM>>>(pAhi, pAlo, pWq, nullptr, pH, Nn, NH * HIDF, nNt);

        int warps = Nn * NH;
        k_attn_logits<<<(warps * 32 + 127) / 128, 128>>>(pH, a1_src, a1_dst, pals1, pald1, HIDF);

        int et = Ee * NH;
        k_edge_max<<<(et + 255) / 256, 256>>>(srcp, dstp, pals1, pald1, pe1, pmk1);
        k_edge_exp<<<(et + 255) / 256, 256>>>(dstp, pe1, pmk1, pden1);
        k_scatter4<<<Ee, 256>>>(srcp, dstp, pH, pe1, pden1, pacc1, HIDF);

        size_t tot = (size_t)Nn * HIDF;
        k_mean<<<(unsigned)((tot + 255) / 256), 256>>>(pacc1, ph1, HIDF, 1);
    }

    // 4) GAT layer 2 -> z
    {
        dim3 grid((NH * OUTF + BN - 1) / BN, (Nn + BM - 1) / BM);
        sgemm_k<<<grid, 256>>>(ph1, W2, nullptr, pH2, Nn, NH * OUTF, HIDF);

        int warps = Nn * NH;
        k_attn_logits<<<(warps * 32 + 127) / 128, 128>>>(pH2, a2_src, a2_dst, pals2, pald2, OUTF);

        int et = Ee * NH;
        k_edge_max<<<(et + 255) / 256, 256>>>(srcp, dstp, pals2, pald2, pe2, pmk2);
        k_edge_exp<<<(et + 255) / 256, 256>>>(dstp, pe2, pmk2, pden2);
        k_scatter<<<Ee, 128>>>(srcp, dstp, pH2, pe2, pden2, pacc2, OUTF);

        size_t tot = (size_t)Nn * OUTF;
        k_mean<<<(unsigned)((tot + 255) / 256), 256>>>(pacc2, z_out, OUTF, 0);
    }

    // 5) MLP head
    k_mlp<<<Nn, MHc>>>(z_out, mlp_w1, mlp_b1, mlp_w2, mlp_b2, flag, yp_out);

    // 6) fc2 -> DSBN stats -> fused apply/ELU/split
    {
        size_t tot = (size_t)Nn * INF_;
        k_fc2<<<(unsigned)((tot + 255) / 256), 256>>>(z_out, fc2_w, fc2_b, px);
        k_cnt<<<(Nn + 255) / 256, 256>>>(y);
        dim3 grid((INF_ + 255) / 256, 128);
        k_dsbn_sum<<<grid, 256>>>(px, y);
        k_dsbn_elu_split<<<(unsigned)splitGrid4, 256>>>(px, y, dsbn_g, dsbn_b, pAhi, pAlo);
    }

    // 7) fc3 -> h3
    {
        dim3 tg((KPAD + 31) / 32, (INF_ + 31) / 32);
        k_splitWT<<<tg, dim3(32, 32)>>>(fc3_w, pWq, INF_, INF_);
        int nNt = (INF_ + 127) / 128;
        gemm_mma3<<<nMt * nNt, 256, GSMEM>>>(pAhi, pAlo, pWq, fc3_b, h3_out, Nn, INF_, nNt);
    }
}